// round 3
// baseline (speedup 1.0000x reference)
#include <cuda_runtime.h>
#include <cuda_bf16.h>
#include <math.h>

// ---------------- problem constants ----------------
#define BATCH 128
#define SEQ   512
#define EMB   300
#define EMBP  304          // padded K (mult of 8)
#define HID   128
#define G4    512          // 4*HID
#define NTAG  12
#define SOS_T 3
#define EOS_T 4
#define NEGV  (-10000.0f)
#define MTOT  (BATCH*SEQ)  // 65536
#define NTOT  1024         // both directions' gates

// ---------------- device scratch (static; no allocations) ----------------
__device__ float g_emb[(size_t)MTOT * EMBP];                  // ~80 MB  padded embeddings
__device__ float g_wt [(size_t)EMBP * NTOT];                  // 1.2 MB  staged [K][N] weights
__device__ float g_bias[NTOT];
__device__ float g_gx [(size_t)2 * MTOT * G4];                // ~268 MB input projections (+bias)
__device__ float g_H  [(size_t)2 * 513 * BATCH * HID];        // ~67 MB  hidden states (slot 0 / 512 = zeros)
__device__ float g_y  [(size_t)MTOT * NTAG];                  // 3 MB    emissions
__device__ int   g_cnt[32];                                   // recurrence sync counters

// ---------------- helpers ----------------
__device__ __forceinline__ int ld_acquire(const int* p) {
    int v;
    asm volatile("ld.acquire.gpu.global.b32 %0, [%1];" : "=r"(v) : "l"(p) : "memory");
    return v;
}
__device__ __forceinline__ float sigf(float x) { return 1.0f / (1.0f + __expf(-x)); }

// ================= stage weights: g_wt[k][n], g_bias =================
__global__ void stage_w_kernel(const float* __restrict__ Wih_f,
                               const float* __restrict__ Wih_b,
                               const float* __restrict__ b_f,
                               const float* __restrict__ b_b) {
    int idx = blockIdx.x * blockDim.x + threadIdx.x;     // over EMBP*NTOT
    if (idx < EMBP * NTOT) {
        int k = idx / NTOT, n = idx % NTOT;
        float v = 0.0f;
        if (k < EMB) v = (n < G4) ? Wih_f[n * EMB + k] : Wih_b[(n - G4) * EMB + k];
        g_wt[idx] = v;
        if (k == 0) g_bias[n] = (n < G4) ? b_f[n] : b_b[n - G4];
    }
}

// ================= gather embeddings (padded) =================
__global__ void gather_kernel(const int* __restrict__ x,
                              const float* __restrict__ embed) {
    int m = blockIdx.x;                 // 0..MTOT-1
    int xi = x[m];
    const float* src = embed + (size_t)xi * EMB;
    float* dst = g_emb + (size_t)m * EMBP;
    for (int k = threadIdx.x; k < EMBP; k += blockDim.x)
        dst[k] = (k < EMB) ? src[k] : 0.0f;
}

// ================= init: counters + zero h slots =================
__global__ void init_kernel() {
    int idx = blockIdx.x * blockDim.x + threadIdx.x;
    if (idx < 32) g_cnt[idx] = 0;
    // fwd zero slot: dir0 slot 0 ; bwd zero slot: dir1 slot 512
    if (idx < BATCH * HID) {
        g_H[idx] = 0.0f;                                              // dir0, slot 0
        g_H[(size_t)513 * BATCH * HID + (size_t)512 * BATCH * HID + idx] = 0.0f; // dir1, slot 512
    }
}

// ================= input-projection SGEMM =================
// C[M=65536][N=1024] = g_emb[M][304] * g_wt[304][N] + bias, scattered into g_gx
__global__ __launch_bounds__(256) void gemm_kernel() {
    __shared__ float As[8][128];
    __shared__ float Bs[8][128];
    const int tid = threadIdx.x;
    const int bm  = blockIdx.y, bn = blockIdx.x;
    const int m0 = bm * 128, n0 = bn * 128;

    const int am = tid >> 1, ak = (tid & 1) * 4;        // A loader: row, k-offset
    const int bk = tid >> 5, bn4 = (tid & 31) * 4;      // B loader: k-row, n-offset
    const int tr = tid >> 4, tc = tid & 15;             // compute: 8x8 per thread

    const float* A = g_emb + (size_t)(m0 + am) * EMBP + ak;
    const float* B = g_wt + (size_t)bk * NTOT + n0 + bn4;

    float acc[8][8];
#pragma unroll
    for (int i = 0; i < 8; ++i)
#pragma unroll
        for (int j = 0; j < 8; ++j) acc[i][j] = 0.0f;

    float4 av = *(const float4*)(A);
    float4 bv = *(const float4*)(B);

    for (int k0 = 0; k0 < EMBP; k0 += 8) {
        As[ak + 0][am] = av.x; As[ak + 1][am] = av.y;
        As[ak + 2][am] = av.z; As[ak + 3][am] = av.w;
        *(float4*)&Bs[bk][bn4] = bv;
        __syncthreads();
        if (k0 + 8 < EMBP) {
            av = *(const float4*)(A + k0 + 8);
            bv = *(const float4*)(B + (size_t)(k0 + 8) * NTOT);
        }
#pragma unroll
        for (int kk = 0; kk < 8; ++kk) {
            float a[8], b[8];
            *(float4*)&a[0] = *(const float4*)&As[kk][tr * 8];
            *(float4*)&a[4] = *(const float4*)&As[kk][tr * 8 + 4];
            *(float4*)&b[0] = *(const float4*)&Bs[kk][tc * 8];
            *(float4*)&b[4] = *(const float4*)&Bs[kk][tc * 8 + 4];
#pragma unroll
            for (int i = 0; i < 8; ++i)
#pragma unroll
                for (int j = 0; j < 8; ++j) acc[i][j] += a[i] * b[j];
        }
        __syncthreads();
    }

    // epilogue: + bias, write to g_gx[dir][m][row]
    const int ng = n0 + tc * 8;           // global n of first column
    const int dir = ng >> 9;
    const int row0 = ng & 511;
    float bias[8];
    *(float4*)&bias[0] = *(const float4*)&g_bias[ng];
    *(float4*)&bias[4] = *(const float4*)&g_bias[ng + 4];
    float* out_base = g_gx + (size_t)dir * MTOT * G4;
#pragma unroll
    for (int i = 0; i < 8; ++i) {
        int m = m0 + tr * 8 + i;
        float4 v0, v1;
        v0.x = acc[i][0] + bias[0]; v0.y = acc[i][1] + bias[1];
        v0.z = acc[i][2] + bias[2]; v0.w = acc[i][3] + bias[3];
        v1.x = acc[i][4] + bias[4]; v1.y = acc[i][5] + bias[5];
        v1.z = acc[i][6] + bias[6]; v1.w = acc[i][7] + bias[7];
        float* p = out_base + (size_t)m * G4 + row0;
        *(float4*)(p)     = v0;
        *(float4*)(p + 4) = v1;
    }
}

// ================= persistent LSTM recurrence =================
// 128 CTAs = 2 dirs x 16 batch-groups(8) x 4 unit-slices(32). 128 threads/CTA.
__global__ __launch_bounds__(128, 1) void recur_kernel(const float* __restrict__ Whh_f,
                                                       const float* __restrict__ Whh_b) {
    const int cta = blockIdx.x;
    const int dir = cta >> 6;
    const int rem = cta & 63;
    const int grp = rem >> 2;
    const int sl  = rem & 3;
    const int b0 = grp * 8;
    const int u0 = sl * 32;
    const int tid = threadIdx.x;
    const int gate = tid >> 5;
    const int ul   = tid & 31;
    const int row  = gate * HID + u0 + ul;   // 0..511

    const float* Whh = dir ? Whh_b : Whh_f;
    float w[128];
#pragma unroll
    for (int k = 0; k < 128; k += 4) {
        float4 v = *(const float4*)(Whh + (size_t)row * HID + k);
        w[k] = v.x; w[k + 1] = v.y; w[k + 2] = v.z; w[k + 3] = v.w;
    }

    __shared__ float hs[8][128];
    __shared__ float pre[4][32][9];   // padded to kill bank conflicts

    // cell state: thread owns items idx=tid and idx=tid+128 -> (b=idx>>5, ul2=idx&31)
    float c0 = 0.0f, c1 = 0.0f;

    float* Hbuf = g_H + (size_t)dir * 513 * BATCH * HID;
    const float* gx = g_gx + (size_t)dir * MTOT * G4;
    int* cnt = &g_cnt[dir * 16 + grp];

    for (int t = 0; t < SEQ; ++t) {
        const int s = dir ? (SEQ - 1 - t) : t;
        const int rslot = dir ? (s + 1) : s;
        const int wslot = dir ? s : (s + 1);

        // gx loads for this step are h-independent: issue BEFORE the wait so
        // their DRAM latency overlaps the inter-CTA barrier spin.
        float acc[8];
#pragma unroll
        for (int b = 0; b < 8; ++b)
            acc[b] = gx[((size_t)(b0 + b) * SEQ + s) * G4 + row];

        if (t > 0) {
            if (tid == 0) {
                while (ld_acquire(cnt) < 4 * t) { __nanosleep(40); }
            }
            __syncthreads();
        }

        // load previous h for the 8 batches
        const float* hp = Hbuf + (size_t)rslot * BATCH * HID + (size_t)b0 * HID;
#pragma unroll
        for (int b = 0; b < 8; ++b) hs[b][tid] = hp[b * HID + tid];
        __syncthreads();

#pragma unroll
        for (int k4 = 0; k4 < 32; ++k4) {
#pragma unroll
            for (int b = 0; b < 8; ++b) {
                float4 hv = *(const float4*)&hs[b][4 * k4];
                acc[b] += w[4 * k4] * hv.x + w[4 * k4 + 1] * hv.y
                        + w[4 * k4 + 2] * hv.z + w[4 * k4 + 3] * hv.w;
            }
        }

#pragma unroll
        for (int b = 0; b < 8; ++b) pre[gate][ul][b] = acc[b];
        __syncthreads();

        // cell update + write h
        float* Hw = Hbuf + (size_t)wslot * BATCH * HID;
        {
            int b = tid >> 5, u2 = tid & 31;
            float iv = pre[0][u2][b], fv = pre[1][u2][b];
            float gv = pre[2][u2][b], ov = pre[3][u2][b];
            c0 = sigf(fv) * c0 + sigf(iv) * tanhf(gv);
            Hw[(size_t)(b0 + b) * HID + u0 + u2] = sigf(ov) * tanhf(c0);
        }
        {
            int b = 4 + (tid >> 5), u2 = tid & 31;
            float iv = pre[0][u2][b], fv = pre[1][u2][b];
            float gv = pre[2][u2][b], ov = pre[3][u2][b];
            c1 = sigf(fv) * c1 + sigf(iv) * tanhf(gv);
            Hw[(size_t)(b0 + b) * HID + u0 + u2] = sigf(ov) * tanhf(c1);
        }

        __threadfence();
        __syncthreads();
        if (tid == 0) atomicAdd(cnt, 1);
    }
}

// ================= output linear: y = [hf,hb] @ Wout^T + bout =================
__global__ __launch_bounds__(64) void outlin_kernel(const float* __restrict__ Wout,
                                                    const float* __restrict__ bout) {
    __shared__ float Ws[NTAG * 256];
    __shared__ float bs[NTAG];
    for (int i = threadIdx.x; i < NTAG * 256; i += 64) Ws[i] = Wout[i];
    if (threadIdx.x < NTAG) bs[threadIdx.x] = bout[threadIdx.x];
    __syncthreads();

    int m = blockIdx.x * 64 + threadIdx.x;    // 0..MTOT-1
    int b = m >> 9, s = m & 511;
    const float* hf = g_H + (size_t)(s + 1) * BATCH * HID + (size_t)b * HID;
    const float* hb = g_H + (size_t)513 * BATCH * HID + (size_t)s * BATCH * HID + (size_t)b * HID;

    float acc[NTAG];
#pragma unroll
    for (int tg = 0; tg < NTAG; ++tg) acc[tg] = bs[tg];

#pragma unroll 4
    for (int j = 0; j < 128; j += 4) {
        float4 hv = *(const float4*)(hf + j);
#pragma unroll
        for (int tg = 0; tg < NTAG; ++tg) {
            const float* wr = &Ws[tg * 256 + j];
            acc[tg] += hv.x * wr[0] + hv.y * wr[1] + hv.z * wr[2] + hv.w * wr[3];
        }
    }
#pragma unroll 4
    for (int j = 0; j < 128; j += 4) {
        float4 hv = *(const float4*)(hb + j);
#pragma unroll
        for (int tg = 0; tg < NTAG; ++tg) {
            const float* wr = &Ws[tg * 256 + 128 + j];
            acc[tg] += hv.x * wr[0] + hv.y * wr[1] + hv.z * wr[2] + hv.w * wr[3];
        }
    }
    float* yo = g_y + (size_t)m * NTAG;
#pragma unroll
    for (int tg = 0; tg < NTAG; ++tg) yo[tg] = acc[tg];
}

// ================= CRF: forward partition + gold score =================
__global__ void crf_kernel(const float* __restrict__ trans,
                           const int* __restrict__ y0,
                           float* __restrict__ out) {
    const int b = blockIdx.x;
    const int lane = threadIdx.x;     // 32 threads

    float tr[NTAG];
#pragma unroll
    for (int j = 0; j < NTAG; ++j)
        tr[j] = (lane < NTAG) ? trans[lane * NTAG + j] : NEGV;

    float sc[NTAG];
#pragma unroll
    for (int j = 0; j < NTAG; ++j) sc[j] = (j == SOS_T) ? 0.0f : NEGV;

    const float* ye = g_y + (size_t)b * SEQ * NTAG;

    for (int t = 0; t < SEQ; ++t) {
        float e = (lane < NTAG) ? ye[t * NTAG + lane] : 0.0f;
        float m = -1e30f;
        float v[NTAG];
#pragma unroll
        for (int j = 0; j < NTAG; ++j) { v[j] = sc[j] + tr[j]; m = fmaxf(m, v[j]); }
        float ssum = 0.0f;
#pragma unroll
        for (int j = 0; j < NTAG; ++j) ssum += __expf(v[j] - m);
        float nw = m + logf(ssum) + e;
#pragma unroll
        for (int j = 0; j < NTAG; ++j) sc[j] = __shfl_sync(0xFFFFFFFFu, nw, j);
    }

    // Z = logsumexp(sc + trans[EOS])
    float zv = (lane < NTAG) ? sc[lane] + trans[EOS_T * NTAG + lane] : -1e30f;
    float zm = zv;
#pragma unroll
    for (int o = 16; o > 0; o >>= 1) zm = fmaxf(zm, __shfl_xor_sync(0xFFFFFFFFu, zm, o));
    float ze = (lane < NTAG) ? __expf(zv - zm) : 0.0f;
#pragma unroll
    for (int o = 16; o > 0; o >>= 1) ze += __shfl_xor_sync(0xFFFFFFFFu, ze, o);
    float Z = zm + logf(ze);

    // gold path score
    const int* yb = y0 + (size_t)b * SEQ;
    float g = 0.0f;
    for (int s = lane; s < SEQ; s += 32) {
        int yt = yb[s];
        int yp = (s == 0) ? SOS_T : yb[s - 1];
        g += ye[s * NTAG + yt] + trans[yt * NTAG + yp];
    }
#pragma unroll
    for (int o = 16; o > 0; o >>= 1) g += __shfl_xor_sync(0xFFFFFFFFu, g, o);

    if (lane == 0) {
        g += trans[EOS_T * NTAG + yb[SEQ - 1]];
        out[b] = Z - g;
    }
}

// ================= launch =================
extern "C" void kernel_launch(void* const* d_in, const int* in_sizes, int n_in,
                              void* d_out, int out_size) {
    const int*   x     = (const int*)d_in[0];
    const int*   y0    = (const int*)d_in[1];
    const float* embed = (const float*)d_in[2];
    const float* Wih_f = (const float*)d_in[3];
    const float* Whh_f = (const float*)d_in[4];
    const float* b_f   = (const float*)d_in[5];
    const float* Wih_b = (const float*)d_in[6];
    const float* Whh_b = (const float*)d_in[7];
    const float* b_b   = (const float*)d_in[8];
    const float* Wout  = (const float*)d_in[9];
    const float* bout  = (const float*)d_in[10];
    const float* trans = (const float*)d_in[11];
    float* out = (float*)d_out;

    stage_w_kernel<<<(EMBP * NTOT + 255) / 256, 256>>>(Wih_f, Wih_b, b_f, b_b);
    gather_kernel<<<MTOT, 128>>>(x, embed);
    init_kernel<<<(BATCH * HID + 127) / 128, 128>>>();
    gemm_kernel<<<dim3(8, 512), 256>>>();
    recur_kernel<<<128, 128>>>(Whh_f, Whh_b);
    outlin_kernel<<<MTOT / 64, 64>>>(Wout, bout);
    crf_kernel<<<BATCH, 32>>>(trans, y0, out);
}

// round 4
// speedup vs baseline: 1.2264x; 1.2264x over previous
#include <cuda_runtime.h>
#include <cuda_bf16.h>
#include <math.h>
#include <stdint.h>

// ---------------- problem constants ----------------
#define BATCH 128
#define SEQ   512
#define EMB   300
#define EMBP  304          // padded K (mult of 16)
#define HID   128
#define G4    512          // 4*HID
#define NTAG  12
#define SOS_T 3
#define EOS_T 4
#define NEGV  (-10000.0f)
#define MTOT  (BATCH*SEQ)  // 65536
#define NTOT  1024         // both directions' gates

// ---------------- device scratch (static; no allocations) ----------------
__device__ float g_emb[(size_t)MTOT * EMBP];                  // ~80 MB  padded embeddings
__device__ float g_wt [(size_t)EMBP * NTOT];                  // 1.2 MB  staged [K][N] weights
__device__ float g_bias[NTOT];
__device__ float g_gx [(size_t)2 * MTOT * G4];                // ~268 MB input projections (+bias)
__device__ float g_H  [(size_t)2 * 513 * BATCH * HID];        // ~67 MB  hidden states (slot 0 / 512 = zeros)
__device__ float g_y  [(size_t)MTOT * NTAG];                  // 3 MB    emissions
__device__ int   g_cnt[32];                                   // recurrence sync counters

// ---------------- helpers ----------------
__device__ __forceinline__ int ld_acquire(const int* p) {
    int v;
    asm volatile("ld.acquire.gpu.global.b32 %0, [%1];" : "=r"(v) : "l"(p) : "memory");
    return v;
}
__device__ __forceinline__ float sigf(float x) { return 1.0f / (1.0f + __expf(-x)); }
__device__ __forceinline__ uint32_t f2tf(float f) {
    uint32_t u; asm("cvt.rna.tf32.f32 %0, %1;" : "=r"(u) : "f"(f)); return u;
}
__device__ __forceinline__ void mma_tf32(float* c, const uint32_t* a, const uint32_t* b) {
    asm volatile(
        "mma.sync.aligned.m16n8k8.row.col.f32.tf32.tf32.f32 "
        "{%0,%1,%2,%3}, {%4,%5,%6,%7}, {%8,%9}, {%0,%1,%2,%3};"
        : "+f"(c[0]), "+f"(c[1]), "+f"(c[2]), "+f"(c[3])
        : "r"(a[0]), "r"(a[1]), "r"(a[2]), "r"(a[3]), "r"(b[0]), "r"(b[1]));
}

// ================= stage weights: g_wt[k][n], g_bias =================
__global__ void stage_w_kernel(const float* __restrict__ Wih_f,
                               const float* __restrict__ Wih_b,
                               const float* __restrict__ b_f,
                               const float* __restrict__ b_b) {
    int idx = blockIdx.x * blockDim.x + threadIdx.x;     // over EMBP*NTOT
    if (idx < EMBP * NTOT) {
        int k = idx / NTOT, n = idx % NTOT;
        float v = 0.0f;
        if (k < EMB) v = (n < G4) ? Wih_f[n * EMB + k] : Wih_b[(n - G4) * EMB + k];
        g_wt[idx] = v;
        if (k == 0) g_bias[n] = (n < G4) ? b_f[n] : b_b[n - G4];
    }
}

// ================= gather embeddings (padded) =================
__global__ void gather_kernel(const int* __restrict__ x,
                              const float* __restrict__ embed) {
    int m = blockIdx.x;                 // 0..MTOT-1
    int xi = x[m];
    const float* src = embed + (size_t)xi * EMB;
    float* dst = g_emb + (size_t)m * EMBP;
    for (int k = threadIdx.x; k < EMBP; k += blockDim.x)
        dst[k] = (k < EMB) ? src[k] : 0.0f;
}

// ================= init: counters + zero h slots =================
__global__ void init_kernel() {
    int idx = blockIdx.x * blockDim.x + threadIdx.x;
    if (idx < 32) g_cnt[idx] = 0;
    // fwd zero slot: dir0 slot 0 ; bwd zero slot: dir1 slot 512
    if (idx < BATCH * HID) {
        g_H[idx] = 0.0f;                                              // dir0, slot 0
        g_H[(size_t)513 * BATCH * HID + (size_t)512 * BATCH * HID + idx] = 0.0f; // dir1, slot 512
    }
}

// ================= input-projection GEMM (TF32 tensor cores) =================
// C[M=65536][N=1024] = g_emb[M][304] * g_wt[304][N] + bias -> g_gx[dir][m][gate]
// CTA: 256 threads (8 warps), tile 128x128, K-step 16.
// Warp grid 2(m) x 4(n): warp tile 64x32 = 4 m-tiles(16) x 4 n-tiles(8), mma m16n8k8.
#define AS_STRIDE 20    // words per A row  (conflict-free frag loads)
#define BS_STRIDE 136   // words per B k-row
__global__ __launch_bounds__(256) void gemm_kernel() {
    __shared__ uint32_t As[128 * AS_STRIDE];   // [m][k] tf32, 10240 B
    __shared__ uint32_t Bs[16 * BS_STRIDE];    // [k][n] tf32,  8704 B

    const int tid = threadIdx.x;
    const int m0 = blockIdx.y * 128, n0 = blockIdx.x * 128;

    const int warp = tid >> 5, lane = tid & 31;
    const int wm = (warp >> 2) * 64, wn = (warp & 3) * 32;
    const int r = lane >> 2, c = lane & 3;

    // loaders
    const int am = tid >> 1, akc = (tid & 1) * 8;          // A: row, k-chunk (2 float4)
    const int bk = tid >> 5, bnc = (tid & 31) * 4;         // B: k-row (and +8), n-chunk

    const float* Ap = g_emb + (size_t)(m0 + am) * EMBP + akc;
    const float* Bp = g_wt + (size_t)bk * NTOT + n0 + bnc;

    float acc[4][4][4];
#pragma unroll
    for (int i = 0; i < 4; ++i)
#pragma unroll
        for (int j = 0; j < 4; ++j)
#pragma unroll
            for (int q = 0; q < 4; ++q) acc[i][j][q] = 0.0f;

    float4 av0 = *(const float4*)(Ap);
    float4 av1 = *(const float4*)(Ap + 4);
    float4 bv0 = *(const float4*)(Bp);
    float4 bv1 = *(const float4*)(Bp + (size_t)8 * NTOT);

    for (int k0 = 0; k0 < EMBP; k0 += 16) {
        // store staged tiles (convert to tf32)
        {
            uint4 ua0 = make_uint4(f2tf(av0.x), f2tf(av0.y), f2tf(av0.z), f2tf(av0.w));
            uint4 ua1 = make_uint4(f2tf(av1.x), f2tf(av1.y), f2tf(av1.z), f2tf(av1.w));
            *(uint4*)&As[am * AS_STRIDE + akc]     = ua0;
            *(uint4*)&As[am * AS_STRIDE + akc + 4] = ua1;
            uint4 ub0 = make_uint4(f2tf(bv0.x), f2tf(bv0.y), f2tf(bv0.z), f2tf(bv0.w));
            uint4 ub1 = make_uint4(f2tf(bv1.x), f2tf(bv1.y), f2tf(bv1.z), f2tf(bv1.w));
            *(uint4*)&Bs[bk * BS_STRIDE + bnc]       = ub0;
            *(uint4*)&Bs[(bk + 8) * BS_STRIDE + bnc] = ub1;
        }
        __syncthreads();
        if (k0 + 16 < EMBP) {
            av0 = *(const float4*)(Ap + k0 + 16);
            av1 = *(const float4*)(Ap + k0 + 20);
            bv0 = *(const float4*)(Bp + (size_t)(k0 + 16) * NTOT);
            bv1 = *(const float4*)(Bp + (size_t)(k0 + 24) * NTOT);
        }
#pragma unroll
        for (int kh = 0; kh < 16; kh += 8) {
            uint32_t af[4][4], bf[4][2];
#pragma unroll
            for (int i = 0; i < 4; ++i) {
                const uint32_t* ap = &As[(wm + i * 16 + r) * AS_STRIDE + kh + c];
                af[i][0] = ap[0];
                af[i][1] = ap[8 * AS_STRIDE];
                af[i][2] = ap[4];
                af[i][3] = ap[8 * AS_STRIDE + 4];
            }
#pragma unroll
            for (int j = 0; j < 4; ++j) {
                const uint32_t* bp = &Bs[(kh + c) * BS_STRIDE + wn + j * 8 + r];
                bf[j][0] = bp[0];
                bf[j][1] = bp[4 * BS_STRIDE];
            }
#pragma unroll
            for (int i = 0; i < 4; ++i)
#pragma unroll
                for (int j = 0; j < 4; ++j)
                    mma_tf32(acc[i][j], af[i], bf[j]);
        }
        __syncthreads();
    }

    // epilogue: + bias, scatter to g_gx[dir][m][gate-row]
    const int dir = n0 >> 9;                    // constant per CTA (n0 mult of 128)
    float* outb = g_gx + (size_t)dir * MTOT * G4;
#pragma unroll
    for (int j = 0; j < 4; ++j) {
        const int n = n0 + wn + j * 8 + c * 2;
        const int grow = n & 511;
        const float2 bias = *(const float2*)&g_bias[n];
#pragma unroll
        for (int i = 0; i < 4; ++i) {
            const int m = m0 + wm + i * 16 + r;
            float2 v0, v1;
            v0.x = acc[i][j][0] + bias.x; v0.y = acc[i][j][1] + bias.y;
            v1.x = acc[i][j][2] + bias.x; v1.y = acc[i][j][3] + bias.y;
            *(float2*)(outb + (size_t)m * G4 + grow)       = v0;
            *(float2*)(outb + (size_t)(m + 8) * G4 + grow) = v1;
        }
    }
}

// ================= persistent LSTM recurrence =================
// 128 CTAs = 2 dirs x 16 batch-groups(8) x 4 unit-slices(32). 128 threads/CTA.
__global__ __launch_bounds__(128, 1) void recur_kernel(const float* __restrict__ Whh_f,
                                                       const float* __restrict__ Whh_b) {
    const int cta = blockIdx.x;
    const int dir = cta >> 6;
    const int rem = cta & 63;
    const int grp = rem >> 2;
    const int sl  = rem & 3;
    const int b0 = grp * 8;
    const int u0 = sl * 32;
    const int tid = threadIdx.x;
    const int gate = tid >> 5;
    const int ul   = tid & 31;
    const int row  = gate * HID + u0 + ul;   // 0..511

    const float* Whh = dir ? Whh_b : Whh_f;
    float w[128];
#pragma unroll
    for (int k = 0; k < 128; k += 4) {
        float4 v = *(const float4*)(Whh + (size_t)row * HID + k);
        w[k] = v.x; w[k + 1] = v.y; w[k + 2] = v.z; w[k + 3] = v.w;
    }

    __shared__ float hs[8][128];
    __shared__ float pre[4][32][9];   // padded to kill bank conflicts

    float c0 = 0.0f, c1 = 0.0f;

    float* Hbuf = g_H + (size_t)dir * 513 * BATCH * HID;
    const float* gx = g_gx + (size_t)dir * MTOT * G4;
    int* cnt = &g_cnt[dir * 16 + grp];

    for (int t = 0; t < SEQ; ++t) {
        const int s = dir ? (SEQ - 1 - t) : t;
        const int rslot = dir ? (s + 1) : s;
        const int wslot = dir ? s : (s + 1);

        // gx loads for this step are h-independent: issue BEFORE the wait so
        // their DRAM latency overlaps the inter-CTA barrier spin.
        float acc[8];
#pragma unroll
        for (int b = 0; b < 8; ++b)
            acc[b] = gx[((size_t)(b0 + b) * SEQ + s) * G4 + row];

        if (t > 0) {
            if (tid == 0) {
                while (ld_acquire(cnt) < 4 * t) { __nanosleep(40); }
            }
            __syncthreads();
        }

        // load previous h for the 8 batches
        const float* hp = Hbuf + (size_t)rslot * BATCH * HID + (size_t)b0 * HID;
#pragma unroll
        for (int b = 0; b < 8; ++b) hs[b][tid] = hp[b * HID + tid];
        __syncthreads();

#pragma unroll
        for (int k4 = 0; k4 < 32; ++k4) {
#pragma unroll
            for (int b = 0; b < 8; ++b) {
                float4 hv = *(const float4*)&hs[b][4 * k4];
                acc[b] += w[4 * k4] * hv.x + w[4 * k4 + 1] * hv.y
                        + w[4 * k4 + 2] * hv.z + w[4 * k4 + 3] * hv.w;
            }
        }

#pragma unroll
        for (int b = 0; b < 8; ++b) pre[gate][ul][b] = acc[b];
        __syncthreads();

        // cell update + write h
        float* Hw = Hbuf + (size_t)wslot * BATCH * HID;
        {
            int b = tid >> 5, u2 = tid & 31;
            float iv = pre[0][u2][b], fv = pre[1][u2][b];
            float gv = pre[2][u2][b], ov = pre[3][u2][b];
            c0 = sigf(fv) * c0 + sigf(iv) * tanhf(gv);
            Hw[(size_t)(b0 + b) * HID + u0 + u2] = sigf(ov) * tanhf(c0);
        }
        {
            int b = 4 + (tid >> 5), u2 = tid & 31;
            float iv = pre[0][u2][b], fv = pre[1][u2][b];
            float gv = pre[2][u2][b], ov = pre[3][u2][b];
            c1 = sigf(fv) * c1 + sigf(iv) * tanhf(gv);
            Hw[(size_t)(b0 + b) * HID + u0 + u2] = sigf(ov) * tanhf(c1);
        }

        __threadfence();
        __syncthreads();
        if (tid == 0) atomicAdd(cnt, 1);
    }
}

// ================= output linear: y = [hf,hb] @ Wout^T + bout =================
__global__ __launch_bounds__(64) void outlin_kernel(const float* __restrict__ Wout,
                                                    const float* __restrict__ bout) {
    __shared__ float Ws[NTAG * 256];
    __shared__ float bs[NTAG];
    for (int i = threadIdx.x; i < NTAG * 256; i += 64) Ws[i] = Wout[i];
    if (threadIdx.x < NTAG) bs[threadIdx.x] = bout[threadIdx.x];
    __syncthreads();

    int m = blockIdx.x * 64 + threadIdx.x;    // 0..MTOT-1
    int b = m >> 9, s = m & 511;
    const float* hf = g_H + (size_t)(s + 1) * BATCH * HID + (size_t)b * HID;
    const float* hb = g_H + (size_t)513 * BATCH * HID + (size_t)s * BATCH * HID + (size_t)b * HID;

    float acc[NTAG];
#pragma unroll
    for (int tg = 0; tg < NTAG; ++tg) acc[tg] = bs[tg];

#pragma unroll 4
    for (int j = 0; j < 128; j += 4) {
        float4 hv = *(const float4*)(hf + j);
#pragma unroll
        for (int tg = 0; tg < NTAG; ++tg) {
            const float* wr = &Ws[tg * 256 + j];
            acc[tg] += hv.x * wr[0] + hv.y * wr[1] + hv.z * wr[2] + hv.w * wr[3];
        }
    }
#pragma unroll 4
    for (int j = 0; j < 128; j += 4) {
        float4 hv = *(const float4*)(hb + j);
#pragma unroll
        for (int tg = 0; tg < NTAG; ++tg) {
            const float* wr = &Ws[tg * 256 + 128 + j];
            acc[tg] += hv.x * wr[0] + hv.y * wr[1] + hv.z * wr[2] + hv.w * wr[3];
        }
    }
    float* yo = g_y + (size_t)m * NTAG;
#pragma unroll
    for (int tg = 0; tg < NTAG; ++tg) yo[tg] = acc[tg];
}

// ================= CRF: forward partition + gold score =================
__global__ void crf_kernel(const float* __restrict__ trans,
                           const int* __restrict__ y0,
                           float* __restrict__ out) {
    const int b = blockIdx.x;
    const int lane = threadIdx.x;     // 32 threads

    float tr[NTAG];
#pragma unroll
    for (int j = 0; j < NTAG; ++j)
        tr[j] = (lane < NTAG) ? trans[lane * NTAG + j] : NEGV;

    float sc[NTAG];
#pragma unroll
    for (int j = 0; j < NTAG; ++j) sc[j] = (j == SOS_T) ? 0.0f : NEGV;

    const float* ye = g_y + (size_t)b * SEQ * NTAG;

    for (int t = 0; t < SEQ; ++t) {
        float e = (lane < NTAG) ? ye[t * NTAG + lane] : 0.0f;
        float m = -1e30f;
        float v[NTAG];
#pragma unroll
        for (int j = 0; j < NTAG; ++j) { v[j] = sc[j] + tr[j]; m = fmaxf(m, v[j]); }
        float ssum = 0.0f;
#pragma unroll
        for (int j = 0; j < NTAG; ++j) ssum += __expf(v[j] - m);
        float nw = m + logf(ssum) + e;
#pragma unroll
        for (int j = 0; j < NTAG; ++j) sc[j] = __shfl_sync(0xFFFFFFFFu, nw, j);
    }

    // Z = logsumexp(sc + trans[EOS])
    float zv = (lane < NTAG) ? sc[lane] + trans[EOS_T * NTAG + lane] : -1e30f;
    float zm = zv;
#pragma unroll
    for (int o = 16; o > 0; o >>= 1) zm = fmaxf(zm, __shfl_xor_sync(0xFFFFFFFFu, zm, o));
    float ze = (lane < NTAG) ? __expf(zv - zm) : 0.0f;
#pragma unroll
    for (int o = 16; o > 0; o >>= 1) ze += __shfl_xor_sync(0xFFFFFFFFu, ze, o);
    float Z = zm + logf(ze);

    // gold path score
    const int* yb = y0 + (size_t)b * SEQ;
    float g = 0.0f;
    for (int s = lane; s < SEQ; s += 32) {
        int yt = yb[s];
        int yp = (s == 0) ? SOS_T : yb[s - 1];
        g += ye[s * NTAG + yt] + trans[yt * NTAG + yp];
    }
#pragma unroll
    for (int o = 16; o > 0; o >>= 1) g += __shfl_xor_sync(0xFFFFFFFFu, g, o);

    if (lane == 0) {
        g += trans[EOS_T * NTAG + yb[SEQ - 1]];
        out[b] = Z - g;
    }
}

// ================= launch =================
extern "C" void kernel_launch(void* const* d_in, const int* in_sizes, int n_in,
                              void* d_out, int out_size) {
    const int*   x     = (const int*)d_in[0];
    const int*   y0    = (const int*)d_in[1];
    const float* embed = (const float*)d_in[2];
    const float* Wih_f = (const float*)d_in[3];
    const float* Whh_f = (const float*)d_in[4];
    const float* b_f   = (const float*)d_in[5];
    const float* Wih_b = (const float*)d_in[6];
    const float* Whh_b = (const float*)d_in[7];
    const float* b_b   = (const float*)d_in[8];
    const float* Wout  = (const float*)d_in[9];
    const float* bout  = (const float*)d_in[10];
    const float* trans = (const float*)d_in[11];
    float* out = (float*)d_out;

    stage_w_kernel<<<(EMBP * NTOT + 255) / 256, 256>>>(Wih_f, Wih_b, b_f, b_b);
    gather_kernel<<<MTOT, 128>>>(x, embed);
    init_kernel<<<(BATCH * HID + 127) / 128, 128>>>();
    gemm_kernel<<<dim3(8, 512), 256>>>();
    recur_kernel<<<128, 128>>>(Whh_f, Whh_b);
    outlin_kernel<<<MTOT / 64, 64>>>(Wout, bout);
    crf_kernel<<<BATCH, 32>>>(trans, y0, out);
}

// round 5
// speedup vs baseline: 1.6303x; 1.3293x over previous
#include <cuda_runtime.h>
#include <cuda_bf16.h>
#include <math.h>
#include <stdint.h>

// ---------------- problem constants ----------------
#define BATCH 128
#define SEQ   512
#define EMB   300
#define EMBP  304          // padded K (mult of 16)
#define HID   128
#define G4    512          // 4*HID
#define NTAG  12
#define SOS_T 3
#define EOS_T 4
#define NEGV  (-10000.0f)
#define MTOT  (BATCH*SEQ)  // 65536
#define NTOT  1024         // both directions' gates

// ---------------- device scratch (static; no allocations) ----------------
__device__ float g_emb[(size_t)MTOT * EMBP];                  // ~80 MB  padded embeddings
__device__ float g_wt [(size_t)EMBP * NTOT];                  // 1.2 MB  staged [K][N] weights
__device__ float g_bias[NTOT];
__device__ float g_gx [(size_t)2 * MTOT * G4];                // ~268 MB input projections (+bias)
__device__ float g_H  [(size_t)2 * 513 * BATCH * HID];        // ~67 MB  hidden states
__device__ float g_y  [(size_t)MTOT * NTAG];                  // 3 MB    emissions

// ---------------- helpers ----------------
__device__ __forceinline__ float sigf(float x) { return 1.0f / (1.0f + __expf(-x)); }
__device__ __forceinline__ uint32_t f2tf(float f) {
    uint32_t u; asm("cvt.rna.tf32.f32 %0, %1;" : "=r"(u) : "f"(f)); return u;
}
__device__ __forceinline__ void mma_tf32(float* c, const uint32_t* a, const uint32_t* b) {
    asm volatile(
        "mma.sync.aligned.m16n8k8.row.col.f32.tf32.tf32.f32 "
        "{%0,%1,%2,%3}, {%4,%5,%6,%7}, {%8,%9}, {%0,%1,%2,%3};"
        : "+f"(c[0]), "+f"(c[1]), "+f"(c[2]), "+f"(c[3])
        : "r"(a[0]), "r"(a[1]), "r"(a[2]), "r"(a[3]), "r"(b[0]), "r"(b[1]));
}
__device__ __forceinline__ uint32_t smem_u32(const void* p) {
    return (uint32_t)__cvta_generic_to_shared(p);
}
__device__ __forceinline__ uint32_t mapa_rank(uint32_t addr, uint32_t rank) {
    uint32_t r;
    asm("mapa.shared::cluster.u32 %0, %1, %2;" : "=r"(r) : "r"(addr), "r"(rank));
    return r;
}
__device__ __forceinline__ void st_clu_f32(uint32_t addr, float v) {
    asm volatile("st.shared::cluster.f32 [%0], %1;" :: "r"(addr), "f"(v) : "memory");
}
__device__ __forceinline__ void st_clu_b32(uint32_t addr, uint32_t v) {
    asm volatile("st.shared::cluster.b32 [%0], %1;" :: "r"(addr), "r"(v) : "memory");
}
__device__ __forceinline__ void mbar_init(uint32_t addr, uint32_t count) {
    asm volatile("mbarrier.init.shared.b64 [%0], %1;" :: "r"(addr), "r"(count) : "memory");
}
__device__ __forceinline__ void mbar_arrive_remote(uint32_t remote_addr) {
    asm volatile("mbarrier.arrive.release.cluster.shared::cluster.b64 _, [%0];"
                 :: "r"(remote_addr) : "memory");
}
__device__ __forceinline__ void mbar_wait_cluster(uint32_t addr, uint32_t parity) {
    asm volatile(
        "{\n\t"
        ".reg .pred P;\n"
        "W_%=:\n\t"
        "mbarrier.try_wait.parity.acquire.cluster.shared::cta.b64 P, [%0], %1, 0x989680;\n\t"
        "@!P bra W_%=;\n\t"
        "}"
        :: "r"(addr), "r"(parity) : "memory");
}

// ================= stage weights: g_wt[k][n], g_bias =================
__global__ void stage_w_kernel(const float* __restrict__ Wih_f,
                               const float* __restrict__ Wih_b,
                               const float* __restrict__ b_f,
                               const float* __restrict__ b_b) {
    int idx = blockIdx.x * blockDim.x + threadIdx.x;     // over EMBP*NTOT
    if (idx < EMBP * NTOT) {
        int k = idx / NTOT, n = idx % NTOT;
        float v = 0.0f;
        if (k < EMB) v = (n < G4) ? Wih_f[n * EMB + k] : Wih_b[(n - G4) * EMB + k];
        g_wt[idx] = v;
        if (k == 0) g_bias[n] = (n < G4) ? b_f[n] : b_b[n - G4];
    }
}

// ================= gather embeddings (padded) =================
__global__ void gather_kernel(const int* __restrict__ x,
                              const float* __restrict__ embed) {
    int m = blockIdx.x;                 // 0..MTOT-1
    int xi = x[m];
    const float* src = embed + (size_t)xi * EMB;
    float* dst = g_emb + (size_t)m * EMBP;
    for (int k = threadIdx.x; k < EMBP; k += blockDim.x)
        dst[k] = (k < EMB) ? src[k] : 0.0f;
}

// ================= input-projection GEMM (TF32 tensor cores) =================
#define AS_STRIDE 20
#define BS_STRIDE 136
__global__ __launch_bounds__(256) void gemm_kernel() {
    __shared__ uint32_t As[128 * AS_STRIDE];
    __shared__ uint32_t Bs[16 * BS_STRIDE];

    const int tid = threadIdx.x;
    const int m0 = blockIdx.y * 128, n0 = blockIdx.x * 128;

    const int warp = tid >> 5, lane = tid & 31;
    const int wm = (warp >> 2) * 64, wn = (warp & 3) * 32;
    const int r = lane >> 2, c = lane & 3;

    const int am = tid >> 1, akc = (tid & 1) * 8;
    const int bk = tid >> 5, bnc = (tid & 31) * 4;

    const float* Ap = g_emb + (size_t)(m0 + am) * EMBP + akc;
    const float* Bp = g_wt + (size_t)bk * NTOT + n0 + bnc;

    float acc[4][4][4];
#pragma unroll
    for (int i = 0; i < 4; ++i)
#pragma unroll
        for (int j = 0; j < 4; ++j)
#pragma unroll
            for (int q = 0; q < 4; ++q) acc[i][j][q] = 0.0f;

    float4 av0 = *(const float4*)(Ap);
    float4 av1 = *(const float4*)(Ap + 4);
    float4 bv0 = *(const float4*)(Bp);
    float4 bv1 = *(const float4*)(Bp + (size_t)8 * NTOT);

    for (int k0 = 0; k0 < EMBP; k0 += 16) {
        {
            uint4 ua0 = make_uint4(f2tf(av0.x), f2tf(av0.y), f2tf(av0.z), f2tf(av0.w));
            uint4 ua1 = make_uint4(f2tf(av1.x), f2tf(av1.y), f2tf(av1.z), f2tf(av1.w));
            *(uint4*)&As[am * AS_STRIDE + akc]     = ua0;
            *(uint4*)&As[am * AS_STRIDE + akc + 4] = ua1;
            uint4 ub0 = make_uint4(f2tf(bv0.x), f2tf(bv0.y), f2tf(bv0.z), f2tf(bv0.w));
            uint4 ub1 = make_uint4(f2tf(bv1.x), f2tf(bv1.y), f2tf(bv1.z), f2tf(bv1.w));
            *(uint4*)&Bs[bk * BS_STRIDE + bnc]       = ub0;
            *(uint4*)&Bs[(bk + 8) * BS_STRIDE + bnc] = ub1;
        }
        __syncthreads();
        if (k0 + 16 < EMBP) {
            av0 = *(const float4*)(Ap + k0 + 16);
            av1 = *(const float4*)(Ap + k0 + 20);
            bv0 = *(const float4*)(Bp + (size_t)(k0 + 16) * NTOT);
            bv1 = *(const float4*)(Bp + (size_t)(k0 + 24) * NTOT);
        }
#pragma unroll
        for (int kh = 0; kh < 16; kh += 8) {
            uint32_t af[4][4], bf[4][2];
#pragma unroll
            for (int i = 0; i < 4; ++i) {
                const uint32_t* ap = &As[(wm + i * 16 + r) * AS_STRIDE + kh + c];
                af[i][0] = ap[0];
                af[i][1] = ap[8 * AS_STRIDE];
                af[i][2] = ap[4];
                af[i][3] = ap[8 * AS_STRIDE + 4];
            }
#pragma unroll
            for (int j = 0; j < 4; ++j) {
                const uint32_t* bp = &Bs[(kh + c) * BS_STRIDE + wn + j * 8 + r];
                bf[j][0] = bp[0];
                bf[j][1] = bp[4 * BS_STRIDE];
            }
#pragma unroll
            for (int i = 0; i < 4; ++i)
#pragma unroll
                for (int j = 0; j < 4; ++j)
                    mma_tf32(acc[i][j], af[i], bf[j]);
        }
        __syncthreads();
    }

    const int dir = n0 >> 9;
    float* outb = g_gx + (size_t)dir * MTOT * G4;
#pragma unroll
    for (int j = 0; j < 4; ++j) {
        const int n = n0 + wn + j * 8 + c * 2;
        const int grow = n & 511;
        const float2 bias = *(const float2*)&g_bias[n];
#pragma unroll
        for (int i = 0; i < 4; ++i) {
            const int m = m0 + wm + i * 16 + r;
            float2 v0, v1;
            v0.x = acc[i][j][0] + bias.x; v0.y = acc[i][j][1] + bias.y;
            v1.x = acc[i][j][2] + bias.x; v1.y = acc[i][j][3] + bias.y;
            *(float2*)(outb + (size_t)m * G4 + grow)       = v0;
            *(float2*)(outb + (size_t)(m + 8) * G4 + grow) = v1;
        }
    }
}

// ================= persistent LSTM recurrence (tensor cores + 2-CTA cluster) ==
// 64 CTAs = 2 dirs x 16 batch-groups(8) x 2 gate-halves. 256 threads (8 warps).
// Cluster of 2: rank0 = gate rows 0..255 (i,f), rank1 = rows 256..511 (g,o).
// Whh half lives in 128 regs/thread as TF32 A-fragments (step-invariant).
// Per step: G[256x8] = Whh_half @ h^T (mma m16n8k8, N=8=batch), gates exchanged
// via DSMEM by owning unit-half, h updated & multicast into both CTAs' hT.
__global__ __launch_bounds__(256, 1) __cluster_dims__(2, 1, 1)
void recur_kernel(const float* __restrict__ Whh_f,
                  const float* __restrict__ Whh_b) {
    __shared__ uint32_t hTs[128 * 8];        // h^T [k=unit][n=batch] tf32
    __shared__ float ex[4 * 64 * 9];         // [gate-type][unit-local][batch(pad9)]
    __shared__ uint64_t mbar[2];             // [0]=gates-ready, [1]=h-ready

    const int cta  = blockIdx.x;
    const int rank = cta & 1;                // gate-half
    const int pair = cta >> 1;
    const int dir  = pair >> 4;
    const int grp  = pair & 15;
    const int b0   = grp * 8;
    const int R0   = rank * 256;             // global gate-row base

    const int tid  = threadIdx.x;
    const int warp = tid >> 5, lane = tid & 31;
    const int r    = lane >> 2, c2 = lane & 3;
    const int wrow = warp * 32;              // local row base of this warp

    const float* Whh = dir ? Whh_b : Whh_f;
    const float* gx  = g_gx + (size_t)dir * MTOT * G4;
    float* Hbuf      = g_H + (size_t)dir * 513 * BATCH * HID;

    // ---- hoist Whh A-fragments into registers (tf32) ----
    uint32_t wfrag[128];                     // [T(2)][ks(16)][q(4)]
#pragma unroll
    for (int T = 0; T < 2; ++T) {
#pragma unroll
        for (int ks = 0; ks < 16; ++ks) {
            const float* base = Whh + (size_t)(R0 + wrow + 16 * T + r) * HID + 8 * ks + c2;
            const int o = (T * 16 + ks) * 4;
            wfrag[o + 0] = f2tf(base[0]);
            wfrag[o + 1] = f2tf(base[8 * HID]);
            wfrag[o + 2] = f2tf(base[4]);
            wfrag[o + 3] = f2tf(base[8 * HID + 4]);
        }
    }

    // ---- init: zero hT, barriers, cluster handshake ----
#pragma unroll
    for (int i = 0; i < 4; ++i) hTs[tid + 256 * i] = 0u;
    const uint32_t mbar0 = smem_u32(&mbar[0]);
    const uint32_t mbar1 = smem_u32(&mbar[1]);
    if (tid == 0) { mbar_init(mbar0, 1); mbar_init(mbar1, 1); }
    __syncthreads();
    asm volatile("barrier.cluster.arrive.aligned;" ::: "memory");
    asm volatile("barrier.cluster.wait.aligned;" ::: "memory");

    const uint32_t peer = rank ^ 1;
    const uint32_t ex_r0 = mapa_rank(smem_u32(ex), 0);
    const uint32_t ex_r1 = mapa_rank(smem_u32(ex), 1);
    const uint32_t hT_self = smem_u32(hTs);
    const uint32_t hT_peer = mapa_rank(hT_self, peer);
    const uint32_t mbar0_peer = mapa_rank(mbar0, peer);
    const uint32_t mbar1_peer = mapa_rank(mbar1, peer);

    // destination routing for this thread's 8 gate values (step-invariant):
    // tiles T=0,1: rows mA = wrow+16T+r, mB = mA+8 ; batches 2*c2, 2*c2+1
    uint32_t gdst[2][2];   // [T][row 0/1] -> smem addr of ex[gt][ul][2*c2]
#pragma unroll
    for (int T = 0; T < 2; ++T) {
#pragma unroll
        for (int h = 0; h < 2; ++h) {
            int m = wrow + 16 * T + r + 8 * h;          // local row 0..255
            int gt = rank * 2 + (m >> 7);
            int u  = m & 127;
            uint32_t base = (u >> 6) ? ex_r1 : ex_r0;
            gdst[T][h] = base + (uint32_t)((gt * 64 * 9 + (u & 63) * 9 + 2 * c2) * 4);
        }
    }

    // h-update assignment: elems e = tid, tid+256 -> ul = e>>3 (0..63), b = e&7
    const int ub  = tid & 7;
    const int ul0 = tid >> 3;            // 0..31
    const int ul1 = ul0 + 32;            // 32..63
    const int ug0 = rank * 64 + ul0;
    const int ug1 = rank * 64 + ul1;
    float cst0 = 0.0f, cst1 = 0.0f;

    // ---- prefetch gx for step 0 ----
    float gxp[8];
    {
        const int s0 = dir ? (SEQ - 1) : 0;
#pragma unroll
        for (int T = 0; T < 2; ++T)
#pragma unroll
            for (int q = 0; q < 4; ++q) {
                int m  = wrow + 16 * T + r + ((q >> 1) ? 8 : 0);
                int bb = 2 * c2 + (q & 1);
                gxp[T * 4 + q] = gx[((size_t)(b0 + bb) * SEQ + s0) * G4 + R0 + m];
            }
    }

    uint32_t parity = 0;
    for (int t = 0; t < SEQ; ++t) {
        const int s = dir ? (SEQ - 1 - t) : t;
        const int wslot = dir ? s : (s + 1);

        // ---- MMA: acc = gx + Whh_half @ h^T ----
        float acc0[4], acc1[4];
#pragma unroll
        for (int q = 0; q < 4; ++q) { acc0[q] = gxp[q]; acc1[q] = gxp[4 + q]; }
#pragma unroll
        for (int ks = 0; ks < 16; ++ks) {
            uint32_t bb[2];
            bb[0] = hTs[(8 * ks + c2) * 8 + r];
            bb[1] = hTs[(8 * ks + c2 + 4) * 8 + r];
            mma_tf32(acc0, &wfrag[(0 * 16 + ks) * 4], bb);
            mma_tf32(acc1, &wfrag[(1 * 16 + ks) * 4], bb);
        }

        // ---- prefetch gx for next step (hide DRAM latency under sync) ----
        if (t + 1 < SEQ) {
            const int sn = dir ? (SEQ - 2 - t) : (t + 1);
#pragma unroll
            for (int T = 0; T < 2; ++T)
#pragma unroll
                for (int q = 0; q < 4; ++q) {
                    int m  = wrow + 16 * T + r + ((q >> 1) ? 8 : 0);
                    int bb = 2 * c2 + (q & 1);
                    gxp[T * 4 + q] = gx[((size_t)(b0 + bb) * SEQ + sn) * G4 + R0 + m];
                }
        }

        // ---- scatter gates to owning CTA's exchange buffer ----
        st_clu_f32(gdst[0][0],     acc0[0]);
        st_clu_f32(gdst[0][0] + 4, acc0[1]);
        st_clu_f32(gdst[0][1],     acc0[2]);
        st_clu_f32(gdst[0][1] + 4, acc0[3]);
        st_clu_f32(gdst[1][0],     acc1[0]);
        st_clu_f32(gdst[1][0] + 4, acc1[1]);
        st_clu_f32(gdst[1][1],     acc1[2]);
        st_clu_f32(gdst[1][1] + 4, acc1[3]);

        __syncthreads();
        if (tid == 0) mbar_arrive_remote(mbar0_peer);
        mbar_wait_cluster(mbar0, parity);

        // ---- h/c update for my 64 units ----
        float* Hw = Hbuf + (size_t)wslot * BATCH * HID + (size_t)b0 * HID;
        {
            float iv = ex[0 * 576 + ul0 * 9 + ub], fv = ex[1 * 576 + ul0 * 9 + ub];
            float gv = ex[2 * 576 + ul0 * 9 + ub], ov = ex[3 * 576 + ul0 * 9 + ub];
            cst0 = sigf(fv) * cst0 + sigf(iv) * tanhf(gv);
            float h = sigf(ov) * tanhf(cst0);
            Hw[ub * HID + ug0] = h;
            uint32_t htf = f2tf(h);
            uint32_t off = (uint32_t)((ug0 * 8 + ub) * 4);
            st_clu_b32(hT_self + off, htf);
            st_clu_b32(hT_peer + off, htf);
        }
        {
            float iv = ex[0 * 576 + ul1 * 9 + ub], fv = ex[1 * 576 + ul1 * 9 + ub];
            float gv = ex[2 * 576 + ul1 * 9 + ub], ov = ex[3 * 576 + ul1 * 9 + ub];
            cst1 = sigf(fv) * cst1 + sigf(iv) * tanhf(gv);
            float h = sigf(ov) * tanhf(cst1);
            Hw[ub * HID + ug1] = h;
            uint32_t htf = f2tf(h);
            uint32_t off = (uint32_t)((ug1 * 8 + ub) * 4);
            st_clu_b32(hT_self + off, htf);
            st_clu_b32(hT_peer + off, htf);
        }

        __syncthreads();
        if (tid == 0) mbar_arrive_remote(mbar1_peer);
        mbar_wait_cluster(mbar1, parity);

        parity ^= 1;
    }

    asm volatile("barrier.cluster.arrive.aligned;" ::: "memory");
    asm volatile("barrier.cluster.wait.aligned;" ::: "memory");
}

// ================= output linear: y = [hf,hb] @ Wout^T + bout =================
__global__ __launch_bounds__(64) void outlin_kernel(const float* __restrict__ Wout,
                                                    const float* __restrict__ bout) {
    __shared__ float Ws[NTAG * 256];
    __shared__ float bs[NTAG];
    for (int i = threadIdx.x; i < NTAG * 256; i += 64) Ws[i] = Wout[i];
    if (threadIdx.x < NTAG) bs[threadIdx.x] = bout[threadIdx.x];
    __syncthreads();

    int m = blockIdx.x * 64 + threadIdx.x;    // 0..MTOT-1
    int b = m >> 9, s = m & 511;
    const float* hf = g_H + (size_t)(s + 1) * BATCH * HID + (size_t)b * HID;
    const float* hb = g_H + (size_t)513 * BATCH * HID + (size_t)s * BATCH * HID + (size_t)b * HID;

    float acc[NTAG];
#pragma unroll
    for (int tg = 0; tg < NTAG; ++tg) acc[tg] = bs[tg];

#pragma unroll 4
    for (int j = 0; j < 128; j += 4) {
        float4 hv = *(const float4*)(hf + j);
#pragma unroll
        for (int tg = 0; tg < NTAG; ++tg) {
            const float* wr = &Ws[tg * 256 + j];
            acc[tg] += hv.x * wr[0] + hv.y * wr[1] + hv.z * wr[2] + hv.w * wr[3];
        }
    }
#pragma unroll 4
    for (int j = 0; j < 128; j += 4) {
        float4 hv = *(const float4*)(hb + j);
#pragma unroll
        for (int tg = 0; tg < NTAG; ++tg) {
            const float* wr = &Ws[tg * 256 + 128 + j];
            acc[tg] += hv.x * wr[0] + hv.y * wr[1] + hv.z * wr[2] + hv.w * wr[3];
        }
    }
    float* yo = g_y + (size_t)m * NTAG;
#pragma unroll
    for (int tg = 0; tg < NTAG; ++tg) yo[tg] = acc[tg];
}

// ================= CRF: forward partition + gold score =================
__global__ void crf_kernel(const float* __restrict__ trans,
                           const int* __restrict__ y0,
                           float* __restrict__ out) {
    const int b = blockIdx.x;
    const int lane = threadIdx.x;     // 32 threads

    float tr[NTAG];
#pragma unroll
    for (int j = 0; j < NTAG; ++j)
        tr[j] = (lane < NTAG) ? trans[lane * NTAG + j] : NEGV;

    float sc[NTAG];
#pragma unroll
    for (int j = 0; j < NTAG; ++j) sc[j] = (j == SOS_T) ? 0.0f : NEGV;

    const float* ye = g_y + (size_t)b * SEQ * NTAG;

    for (int t = 0; t < SEQ; ++t) {
        float e = (lane < NTAG) ? ye[t * NTAG + lane] : 0.0f;
        float m = -1e30f;
        float v[NTAG];
#pragma unroll
        for (int j = 0; j < NTAG; ++j) { v[j] = sc[j] + tr[j]; m = fmaxf(m, v[j]); }
        float ssum = 0.0f;
#pragma unroll
        for (int j = 0; j < NTAG; ++j) ssum += __expf(v[j] - m);
        float nw = m + logf(ssum) + e;
#pragma unroll
        for (int j = 0; j < NTAG; ++j) sc[j] = __shfl_sync(0xFFFFFFFFu, nw, j);
    }

    float zv = (lane < NTAG) ? sc[lane] + trans[EOS_T * NTAG + lane] : -1e30f;
    float zm = zv;
#pragma unroll
    for (int o = 16; o > 0; o >>= 1) zm = fmaxf(zm, __shfl_xor_sync(0xFFFFFFFFu, zm, o));
    float ze = (lane < NTAG) ? __expf(zv - zm) : 0.0f;
#pragma unroll
    for (int o = 16; o > 0; o >>= 1) ze += __shfl_xor_sync(0xFFFFFFFFu, ze, o);
    float Z = zm + logf(ze);

    const int* yb = y0 + (size_t)b * SEQ;
    float g = 0.0f;
    for (int s = lane; s < SEQ; s += 32) {
        int yt = yb[s];
        int yp = (s == 0) ? SOS_T : yb[s - 1];
        g += ye[s * NTAG + yt] + trans[yt * NTAG + yp];
    }
#pragma unroll
    for (int o = 16; o > 0; o >>= 1) g += __shfl_xor_sync(0xFFFFFFFFu, g, o);

    if (lane == 0) {
        g += trans[EOS_T * NTAG + yb[SEQ - 1]];
        out[b] = Z - g;
    }
}

// ================= launch =================
extern "C" void kernel_launch(void* const* d_in, const int* in_sizes, int n_in,
                              void* d_out, int out_size) {
    const int*   x     = (const int*)d_in[0];
    const int*   y0    = (const int*)d_in[1];
    const float* embed = (const float*)d_in[2];
    const float* Wih_f = (const float*)d_in[3];
    const float* Whh_f = (const float*)d_in[4];
    const float* b_f   = (const float*)d_in[5];
    const float* Wih_b = (const float*)d_in[6];
    const float* Whh_b = (const float*)d_in[7];
    const float* b_b   = (const float*)d_in[8];
    const float* Wout  = (const float*)d_in[9];
    const float* bout  = (const float*)d_in[10];
    const float* trans = (const float*)d_in[11];
    float* out = (float*)d_out;

    stage_w_kernel<<<(EMBP * NTOT + 255) / 256, 256>>>(Wih_f, Wih_b, b_f, b_b);
    gather_kernel<<<MTOT, 128>>>(x, embed);
    gemm_kernel<<<dim3(8, 512), 256>>>();
    recur_kernel<<<64, 256>>>(Whh_f, Whh_b);
    outlin_kernel<<<MTOT / 64, 64>>>(Wout, bout);
    crf_kernel<<<BATCH, 32>>>(trans, y0, out);
}

// round 7
// speedup vs baseline: 1.9637x; 1.2045x over previous
#include <cuda_runtime.h>
#include <cuda_bf16.h>
#include <math.h>
#include <stdint.h>

// ---------------- problem constants ----------------
#define BATCH 128
#define SEQ   512
#define EMB   300
#define EMBP  304          // padded K (mult of 16)
#define HID   128
#define G4    512          // 4*HID
#define NTAG  12
#define SOS_T 3
#define EOS_T 4
#define NEGV  (-10000.0f)
#define MTOT  (BATCH*SEQ)  // 65536
#define NTOT  1024         // both directions' gates

// ---------------- device scratch (static; no allocations) ----------------
__device__ float g_emb[(size_t)MTOT * EMBP];                  // ~80 MB  padded embeddings
__device__ float g_wt [(size_t)EMBP * NTOT];                  // 1.2 MB  staged [K][N] weights
__device__ float g_bias[NTOT];
__device__ __nv_bfloat16 g_gx [(size_t)2 * MTOT * G4];        // ~134 MB input projections (+bias), bf16
__device__ float g_H  [(size_t)2 * 513 * BATCH * HID];        // ~67 MB  hidden states
__device__ float g_y  [(size_t)MTOT * NTAG];                  // 3 MB    emissions

// ---------------- helpers ----------------
__device__ __forceinline__ float tanh_ap(float x) {
    float y; asm("tanh.approx.f32 %0, %1;" : "=f"(y) : "f"(x)); return y;
}
__device__ __forceinline__ float sig_ap(float x) {
    return 0.5f * tanh_ap(0.5f * x) + 0.5f;
}
__device__ __forceinline__ uint32_t f2tf(float f) {
    uint32_t u; asm("cvt.rna.tf32.f32 %0, %1;" : "=r"(u) : "f"(f)); return u;
}
__device__ __forceinline__ void mma_tf32(float* c, const uint32_t* a, const uint32_t* b) {
    asm volatile(
        "mma.sync.aligned.m16n8k8.row.col.f32.tf32.tf32.f32 "
        "{%0,%1,%2,%3}, {%4,%5,%6,%7}, {%8,%9}, {%0,%1,%2,%3};"
        : "+f"(c[0]), "+f"(c[1]), "+f"(c[2]), "+f"(c[3])
        : "r"(a[0]), "r"(a[1]), "r"(a[2]), "r"(a[3]), "r"(b[0]), "r"(b[1]));
}
__device__ __forceinline__ uint32_t smem_u32(const void* p) {
    return (uint32_t)__cvta_generic_to_shared(p);
}
__device__ __forceinline__ uint32_t mapa_rank(uint32_t addr, uint32_t rank) {
    uint32_t r;
    asm("mapa.shared::cluster.u32 %0, %1, %2;" : "=r"(r) : "r"(addr), "r"(rank));
    return r;
}
__device__ __forceinline__ void st_clu_b32(uint32_t addr, uint32_t v) {
    asm volatile("st.shared::cluster.b32 [%0], %1;" :: "r"(addr), "r"(v) : "memory");
}
__device__ __forceinline__ void mbar_init(uint32_t addr, uint32_t count) {
    asm volatile("mbarrier.init.shared.b64 [%0], %1;" :: "r"(addr), "r"(count) : "memory");
}
__device__ __forceinline__ void mbar_arrive_remote(uint32_t remote_addr) {
    asm volatile("mbarrier.arrive.release.cluster.shared::cluster.b64 _, [%0];"
                 :: "r"(remote_addr) : "memory");
}
__device__ __forceinline__ void mbar_wait_cluster(uint32_t addr, uint32_t parity) {
    asm volatile(
        "{\n\t"
        ".reg .pred P;\n"
        "W_%=:\n\t"
        "mbarrier.try_wait.parity.acquire.cluster.shared::cta.b64 P, [%0], %1, 0x989680;\n\t"
        "@!P bra W_%=;\n\t"
        "}"
        :: "r"(addr), "r"(parity) : "memory");
}

// ================= stage weights: g_wt[k][n], g_bias =================
__global__ void stage_w_kernel(const float* __restrict__ Wih_f,
                               const float* __restrict__ Wih_b,
                               const float* __restrict__ b_f,
                               const float* __restrict__ b_b) {
    int idx = blockIdx.x * blockDim.x + threadIdx.x;     // over EMBP*NTOT
    if (idx < EMBP * NTOT) {
        int k = idx / NTOT, n = idx % NTOT;
        float v = 0.0f;
        if (k < EMB) v = (n < G4) ? Wih_f[n * EMB + k] : Wih_b[(n - G4) * EMB + k];
        g_wt[idx] = v;
        if (k == 0) g_bias[n] = (n < G4) ? b_f[n] : b_b[n - G4];
    }
}

// ================= gather embeddings (padded) =================
__global__ void gather_kernel(const int* __restrict__ x,
                              const float* __restrict__ embed) {
    int m = blockIdx.x;                 // 0..MTOT-1
    int xi = x[m];
    const float* src = embed + (size_t)xi * EMB;
    float* dst = g_emb + (size_t)m * EMBP;
    for (int k = threadIdx.x; k < EMBP; k += blockDim.x)
        dst[k] = (k < EMB) ? src[k] : 0.0f;
}

// ================= input-projection GEMM (TF32 tensor cores, bf16 output) =====
#define AS_STRIDE 20
#define BS_STRIDE 136
__global__ __launch_bounds__(256) void gemm_kernel() {
    __shared__ uint32_t As[128 * AS_STRIDE];
    __shared__ uint32_t Bs[16 * BS_STRIDE];

    const int tid = threadIdx.x;
    const int m0 = blockIdx.y * 128, n0 = blockIdx.x * 128;

    const int warp = tid >> 5, lane = tid & 31;
    const int wm = (warp >> 2) * 64, wn = (warp & 3) * 32;
    const int r = lane >> 2, c = lane & 3;

    const int am = tid >> 1, akc = (tid & 1) * 8;
    const int bk = tid >> 5, bnc = (tid & 31) * 4;

    const float* Ap = g_emb + (size_t)(m0 + am) * EMBP + akc;
    const float* Bp = g_wt + (size_t)bk * NTOT + n0 + bnc;

    float acc[4][4][4];
#pragma unroll
    for (int i = 0; i < 4; ++i)
#pragma unroll
        for (int j = 0; j < 4; ++j)
#pragma unroll
            for (int q = 0; q < 4; ++q) acc[i][j][q] = 0.0f;

    float4 av0 = *(const float4*)(Ap);
    float4 av1 = *(const float4*)(Ap + 4);
    float4 bv0 = *(const float4*)(Bp);
    float4 bv1 = *(const float4*)(Bp + (size_t)8 * NTOT);

    for (int k0 = 0; k0 < EMBP; k0 += 16) {
        {
            uint4 ua0 = make_uint4(f2tf(av0.x), f2tf(av0.y), f2tf(av0.z), f2tf(av0.w));
            uint4 ua1 = make_uint4(f2tf(av1.x), f2tf(av1.y), f2tf(av1.z), f2tf(av1.w));
            *(uint4*)&As[am * AS_STRIDE + akc]     = ua0;
            *(uint4*)&As[am * AS_STRIDE + akc + 4] = ua1;
            uint4 ub0 = make_uint4(f2tf(bv0.x), f2tf(bv0.y), f2tf(bv0.z), f2tf(bv0.w));
            uint4 ub1 = make_uint4(f2tf(bv1.x), f2tf(bv1.y), f2tf(bv1.z), f2tf(bv1.w));
            *(uint4*)&Bs[bk * BS_STRIDE + bnc]       = ub0;
            *(uint4*)&Bs[(bk + 8) * BS_STRIDE + bnc] = ub1;
        }
        __syncthreads();
        if (k0 + 16 < EMBP) {
            av0 = *(const float4*)(Ap + k0 + 16);
            av1 = *(const float4*)(Ap + k0 + 20);
            bv0 = *(const float4*)(Bp + (size_t)(k0 + 16) * NTOT);
            bv1 = *(const float4*)(Bp + (size_t)(k0 + 24) * NTOT);
        }
#pragma unroll
        for (int kh = 0; kh < 16; kh += 8) {
            uint32_t af[4][4], bf[4][2];
#pragma unroll
            for (int i = 0; i < 4; ++i) {
                const uint32_t* ap = &As[(wm + i * 16 + r) * AS_STRIDE + kh + c];
                af[i][0] = ap[0];
                af[i][1] = ap[8 * AS_STRIDE];
                af[i][2] = ap[4];
                af[i][3] = ap[8 * AS_STRIDE + 4];
            }
#pragma unroll
            for (int j = 0; j < 4; ++j) {
                const uint32_t* bp = &Bs[(kh + c) * BS_STRIDE + wn + j * 8 + r];
                bf[j][0] = bp[0];
                bf[j][1] = bp[4 * BS_STRIDE];
            }
#pragma unroll
            for (int i = 0; i < 4; ++i)
#pragma unroll
                for (int j = 0; j < 4; ++j)
                    mma_tf32(acc[i][j], af[i], bf[j]);
        }
        __syncthreads();
    }

    const int dir = n0 >> 9;
    __nv_bfloat16* outb = g_gx + (size_t)dir * MTOT * G4;
#pragma unroll
    for (int j = 0; j < 4; ++j) {
        const int n = n0 + wn + j * 8 + c * 2;
        const int grow = n & 511;
        const float2 bias = *(const float2*)&g_bias[n];
#pragma unroll
        for (int i = 0; i < 4; ++i) {
            const int m = m0 + wm + i * 16 + r;
            __nv_bfloat162 p0 = __floats2bfloat162_rn(acc[i][j][0] + bias.x,
                                                      acc[i][j][1] + bias.y);
            __nv_bfloat162 p1 = __floats2bfloat162_rn(acc[i][j][2] + bias.x,
                                                      acc[i][j][3] + bias.y);
            *(__nv_bfloat162*)(outb + (size_t)m * G4 + grow)       = p0;
            *(__nv_bfloat162*)(outb + (size_t)(m + 8) * G4 + grow) = p1;
        }
    }
}

// ================= persistent LSTM recurrence (tensor cores + 2-CTA cluster) ==
// 64 CTAs = 2 dirs x 16 batch-groups(8) x 2 UNIT-halves. 256 threads (8 warps).
// Partition by hidden unit: rank owns units rank*64..+63 and computes ALL FOUR
// gates for them (local rows m=0..255 map to global gate row
// (m>>6)*128 + rank*64 + (m&63)). Gates never cross the cluster; only h does
// (2KB tf32, double-buffered by step parity, ONE mbarrier handshake per step).
#define EXPAD 12
__global__ __launch_bounds__(256, 1) __cluster_dims__(2, 1, 1)
void recur_kernel(const float* __restrict__ Whh_f,
                  const float* __restrict__ Whh_b) {
    __shared__ uint32_t hTs[2][128 * 8];     // h^T [k=unit][n=batch] tf32, 2 buffers
    __shared__ float ex[4 * 64 * EXPAD];     // [gate-type][unit-local][batch(pad)]
    __shared__ uint64_t mbar;                // h-ready barrier

    const int cta  = blockIdx.x;
    const int rank = cta & 1;                // unit-half
    const int pair = cta >> 1;
    const int dir  = pair >> 4;
    const int grp  = pair & 15;
    const int b0   = grp * 8;

    const int tid  = threadIdx.x;
    const int warp = tid >> 5, lane = tid & 31;
    const int r    = lane >> 2, c2 = lane & 3;
    const int wrow = warp * 32;              // local row base of this warp

    const float* Whh = dir ? Whh_b : Whh_f;
    const __nv_bfloat16* gx = g_gx + (size_t)dir * MTOT * G4;
    float* Hbuf = g_H + (size_t)dir * 513 * BATCH * HID;

    // local row -> global gate row
    auto growf = [&](int m) { return ((m >> 6) << 7) + rank * 64 + (m & 63); };

    // ---- hoist Whh A-fragments into registers (tf32) ----
    uint32_t wfrag[128];                     // [T(2)][ks(16)][q(4)]
#pragma unroll
    for (int T = 0; T < 2; ++T) {
#pragma unroll
        for (int ks = 0; ks < 16; ++ks) {
            const int gr = growf(wrow + 16 * T + r);
            const float* base = Whh + (size_t)gr * HID + 8 * ks + c2;
            const int o = (T * 16 + ks) * 4;
            wfrag[o + 0] = f2tf(base[0]);
            wfrag[o + 1] = f2tf(base[8 * HID]);
            wfrag[o + 2] = f2tf(base[4]);
            wfrag[o + 3] = f2tf(base[8 * HID + 4]);
        }
    }

    // ---- init: zero hT buffers, barrier, cluster handshake ----
#pragma unroll
    for (int i = 0; i < 4; ++i) { hTs[0][tid + 256 * i] = 0u; hTs[1][tid + 256 * i] = 0u; }
    const uint32_t mbar_a = smem_u32(&mbar);
    if (tid == 0) mbar_init(mbar_a, 1);
    __syncthreads();
    asm volatile("barrier.cluster.arrive.aligned;" ::: "memory");
    asm volatile("barrier.cluster.wait.aligned;" ::: "memory");

    const uint32_t peer = rank ^ 1;
    const uint32_t mbar_peer = mapa_rank(mbar_a, peer);
    const uint32_t hTp0 = mapa_rank(smem_u32(&hTs[0][0]), peer);
    const uint32_t hTp1 = mapa_rank(smem_u32(&hTs[1][0]), peer);

    // gate scatter destinations (local smem, step-invariant)
    float2* sdst[2][2];
#pragma unroll
    for (int T = 0; T < 2; ++T)
#pragma unroll
        for (int h = 0; h < 2; ++h) {
            int m = wrow + 16 * T + r + 8 * h;
            sdst[T][h] = (float2*)&ex[(m >> 6) * 64 * EXPAD + (m & 63) * EXPAD + 2 * c2];
        }

    // h-update assignment: elems e = tid, tid+256 -> ul = e>>3 (0..63), b = e&7
    const int ub  = tid & 7;
    const int ul0 = tid >> 3;            // 0..31
    const int ul1 = ul0 + 32;            // 32..63
    const int ug0 = rank * 64 + ul0;
    const int ug1 = rank * 64 + ul1;
    const uint32_t hoff0 = (uint32_t)((ug0 * 8 + ub) * 4);
    const uint32_t hoff1 = (uint32_t)((ug1 * 8 + ub) * 4);
    float cst0 = 0.0f, cst1 = 0.0f;

    // gx row indices for this thread's 8 values
    int gr8[4];
#pragma unroll
    for (int T = 0; T < 2; ++T)
#pragma unroll
        for (int h = 0; h < 2; ++h)
            gr8[T * 2 + h] = growf(wrow + 16 * T + r + 8 * h);

    // ---- prefetch gx for step 0 ----
    float gxp[8];
    {
        const int s0 = dir ? (SEQ - 1) : 0;
#pragma unroll
        for (int T = 0; T < 2; ++T)
#pragma unroll
            for (int q = 0; q < 4; ++q) {
                int bb = 2 * c2 + (q & 1);
                gxp[T * 4 + q] = __bfloat162float(
                    gx[((size_t)(b0 + bb) * SEQ + s0) * G4 + gr8[T * 2 + (q >> 1)]]);
            }
    }

    for (int t = 0; t < SEQ; ++t) {
        const int s = dir ? (SEQ - 1 - t) : t;
        const int wslot = dir ? s : (s + 1);
        const int buf = t & 1;

        // ---- MMA: acc = gx + Whh_rows @ h^T ----
        float acc0[4], acc1[4];
#pragma unroll
        for (int q = 0; q < 4; ++q) { acc0[q] = gxp[q]; acc1[q] = gxp[4 + q]; }
#pragma unroll
        for (int ks = 0; ks < 16; ++ks) {
            uint32_t bb[2];
            bb[0] = hTs[buf][(8 * ks + c2) * 8 + r];
            bb[1] = hTs[buf][(8 * ks + c2 + 4) * 8 + r];
            mma_tf32(acc0, &wfrag[(0 * 16 + ks) * 4], bb);
            mma_tf32(acc1, &wfrag[(1 * 16 + ks) * 4], bb);
        }

        // ---- prefetch gx for next step ----
        if (t + 1 < SEQ) {
            const int sn = dir ? (SEQ - 2 - t) : (t + 1);
#pragma unroll
            for (int T = 0; T < 2; ++T)
#pragma unroll
                for (int q = 0; q < 4; ++q) {
                    int bb = 2 * c2 + (q & 1);
                    gxp[T * 4 + q] = __bfloat162float(
                        gx[((size_t)(b0 + bb) * SEQ + sn) * G4 + gr8[T * 2 + (q >> 1)]]);
                }
        }

        // ---- scatter gates to LOCAL exchange buffer ----
        *sdst[0][0] = make_float2(acc0[0], acc0[1]);
        *sdst[0][1] = make_float2(acc0[2], acc0[3]);
        *sdst[1][0] = make_float2(acc1[0], acc1[1]);
        *sdst[1][1] = make_float2(acc1[2], acc1[3]);
        __syncthreads();

        // ---- h/c update for my 64 units; publish h to both hT buffers ----
        float* Hw = Hbuf + (size_t)wslot * BATCH * HID + (size_t)b0 * HID;
        const uint32_t hTpeer = (buf ? hTp0 : hTp1);   // write buffer buf^1
        {
            const float* e0 = &ex[ul0 * EXPAD + ub];
            float iv = e0[0], fv = e0[64 * EXPAD], gv = e0[128 * EXPAD], ov = e0[192 * EXPAD];
            cst0 = sig_ap(fv) * cst0 + sig_ap(iv) * tanh_ap(gv);
            float h = sig_ap(ov) * tanh_ap(cst0);
            Hw[ub * HID + ug0] = h;
            uint32_t htf = f2tf(h);
            hTs[buf ^ 1][ug0 * 8 + ub] = htf;
            st_clu_b32(hTpeer + hoff0, htf);
        }
        {
            const float* e1 = &ex[ul1 * EXPAD + ub];
            float iv = e1[0], fv = e1[64 * EXPAD], gv = e1[128 * EXPAD], ov = e1[192 * EXPAD];
            cst1 = sig_ap(fv) * cst1 + sig_ap(iv) * tanh_ap(gv);
            float h = sig_ap(ov) * tanh_ap(cst1);
            Hw[ub * HID + ug1] = h;
            uint32_t htf = f2tf(h);
            hTs[buf ^ 1][ug1 * 8 + ub] = htf;
            st_clu_b32(hTpeer + hoff1, htf);
        }

        __syncthreads();
        if (tid == 0) mbar_arrive_remote(mbar_peer);
        mbar_wait_cluster(mbar_a, (uint32_t)(t & 1));
    }

    asm volatile("barrier.cluster.arrive.aligned;" ::: "memory");
    asm volatile("barrier.cluster.wait.aligned;" ::: "memory");
}

// ================= output linear: y = [hf,hb] @ Wout^T + bout =================
__global__ __launch_bounds__(64) void outlin_kernel(const float* __restrict__ Wout,
                                                    const float* __restrict__ bout) {
    __shared__ float Ws[NTAG * 256];
    __shared__ float bs[NTAG];
    for (int i = threadIdx.x; i < NTAG * 256; i += 64) Ws[i] = Wout[i];
    if (threadIdx.x < NTAG) bs[threadIdx.x] = bout[threadIdx.x];
    __syncthreads();

    int m = blockIdx.x * 64 + threadIdx.x;    // 0..MTOT-1
    int b = m >> 9, s = m & 511;
    const float* hf = g_H + (size_t)(s + 1) * BATCH * HID + (size_t)b * HID;
    const float* hb = g_H + (size_t)513 * BATCH * HID + (size_t)s * BATCH * HID + (size_t)b * HID;

    float acc[NTAG];
#pragma unroll
    for (int tg = 0; tg < NTAG; ++tg) acc[tg] = bs[tg];

#pragma unroll 4
    for (int j = 0; j < 128; j += 4) {
        float4 hv = *(const float4*)(hf + j);
#pragma unroll
        for (int tg = 0; tg < NTAG; ++tg) {
            const float* wr = &Ws[tg * 256 + j];
            acc[tg] += hv.x * wr[0] + hv.y * wr[1] + hv.z * wr[2] + hv.w * wr[3];
        }
    }
#pragma unroll 4
    for (int j = 0; j < 128; j += 4) {
        float4 hv = *(const float4*)(hb + j);
#pragma unroll
        for (int tg = 0; tg < NTAG; ++tg) {
            const float* wr = &Ws[tg * 256 + 128 + j];
            acc[tg] += hv.x * wr[0] + hv.y * wr[1] + hv.z * wr[2] + hv.w * wr[3];
        }
    }
    float* yo = g_y + (size_t)m * NTAG;
#pragma unroll
    for (int tg = 0; tg < NTAG; ++tg) yo[tg] = acc[tg];
}

// ================= CRF: forward partition + gold score =================
__global__ void crf_kernel(const float* __restrict__ trans,
                           const int* __restrict__ y0,
                           float* __restrict__ out) {
    const int b = blockIdx.x;
    const int lane = threadIdx.x;     // 32 threads

    float tr[NTAG];
#pragma unroll
    for (int j = 0; j < NTAG; ++j)
        tr[j] = (lane < NTAG) ? trans[lane * NTAG + j] : NEGV;

    float sc[NTAG];
#pragma unroll
    for (int j = 0; j < NTAG; ++j) sc[j] = (j == SOS_T) ? 0.0f : NEGV;

    const float* ye = g_y + (size_t)b * SEQ * NTAG;

    for (int t = 0; t < SEQ; ++t) {
        float e = (lane < NTAG) ? ye[t * NTAG + lane] : 0.0f;
        float m = -1e30f;
        float v[NTAG];
#pragma unroll
        for (int j = 0; j < NTAG; ++j) { v[j] = sc[j] + tr[j]; m = fmaxf(m, v[j]); }
        float ssum = 0.0f;
#pragma unroll
        for (int j = 0; j < NTAG; ++j) ssum += __expf(v[j] - m);
        float nw = m + logf(ssum) + e;
#pragma unroll
        for (int j = 0; j < NTAG; ++j) sc[j] = __shfl_sync(0xFFFFFFFFu, nw, j);
    }

    float zv = (lane < NTAG) ? sc[lane] + trans[EOS_T * NTAG + lane] : -1e30f;
    float zm = zv;
#pragma unroll
    for (int o = 16; o > 0; o >>= 1) zm = fmaxf(zm, __shfl_xor_sync(0xFFFFFFFFu, zm, o));
    float ze = (lane < NTAG) ? __expf(zv - zm) : 0.0f;
#pragma unroll
    for (int o = 16; o > 0; o >>= 1) ze += __shfl_xor_sync(0xFFFFFFFFu, ze, o);
    float Z = zm + logf(ze);

    const int* yb = y0 + (size_t)b * SEQ;
    float g = 0.0f;
    for (int s = lane; s < SEQ; s += 32) {
        int yt = yb[s];
        int yp = (s == 0) ? SOS_T : yb[s - 1];
        g += ye[s * NTAG + yt] + trans[yt * NTAG + yp];
    }
#pragma unroll
    for (int o = 16; o > 0; o >>= 1) g += __shfl_xor_sync(0xFFFFFFFFu, g, o);

    if (lane == 0) {
        g += trans[EOS_T * NTAG + yb[SEQ - 1]];
        out[b] = Z - g;
    }
}

// ================= launch =================
extern "C" void kernel_launch(void* const* d_in, const int* in_sizes, int n_in,
                              void* d_out, int out_size) {
    const int*   x     = (const int*)d_in[0];
    const int*   y0    = (const int*)d_in[1];
    const float* embed = (const float*)d_in[2];
    const float* Wih_f = (const float*)d_in[3];
    const float* Whh_f = (const float*)d_in[4];
    const float* b_f   = (const float*)d_in[5];
    const float* Wih_b = (const float*)d_in[6];
    const float* Whh_b = (const float*)d_in[7];
    const float* b_b   = (const float*)d_in[8];
    const float* Wout  = (const float*)d_in[9];
    const float* bout  = (const float*)d_in[10];
    const float* trans = (const float*)d_in[11];
    float* out = (float*)d_out;

    stage_w_kernel<<<(EMBP * NTOT + 255) / 256, 256>>>(Wih_f, Wih_b, b_f, b_b);
    gather_kernel<<<MTOT, 128>>>(x, embed);
    gemm_kernel<<<dim3(8, 512), 256>>>();
    recur_kernel<<<64, 256>>>(Whh_f, Whh_b);
    outlin_kernel<<<MTOT / 64, 64>>>(Wout, bout);
    crf_kernel<<<BATCH, 32>>>(trans, y0, out);
}

// round 12
// speedup vs baseline: 2.3355x; 1.1894x over previous
#include <cuda_runtime.h>
#include <cuda_bf16.h>
#include <math.h>
#include <stdint.h>

// ---------------- problem constants ----------------
#define BATCH 128
#define SEQ   512
#define EMB   300
#define EMBP  304          // padded K (mult of 16)
#define HID   128
#define G4    512          // 4*HID
#define NTAG  12
#define SOS_T 3
#define EOS_T 4
#define NEGV  (-10000.0f)
#define MTOT  (BATCH*SEQ)  // 65536
#define NTOT  1024         // both directions' gates

// ---------------- device scratch (static; no allocations) ----------------
__device__ float g_emb[(size_t)MTOT * EMBP];                  // ~80 MB  padded embeddings
__device__ float g_wt [(size_t)EMBP * NTOT];                  // 1.2 MB  staged [K][N] weights
__device__ float g_bias[NTOT];
__device__ __nv_bfloat16 g_gx [(size_t)2 * MTOT * G4];        // ~134 MB input projections (+bias), bf16
__device__ float g_H  [(size_t)2 * 513 * BATCH * HID];        // ~67 MB  hidden states
__device__ float g_y  [(size_t)MTOT * NTAG];                  // 3 MB    emissions

// ---------------- helpers ----------------
__device__ __forceinline__ float tanh_ap(float x) {
    float y; asm("tanh.approx.f32 %0, %1;" : "=f"(y) : "f"(x)); return y;
}
__device__ __forceinline__ float sig_ap(float x) {
    return 0.5f * tanh_ap(0.5f * x) + 0.5f;
}
__device__ __forceinline__ uint32_t f2tf(float f) {
    uint32_t u; asm("cvt.rna.tf32.f32 %0, %1;" : "=r"(u) : "f"(f)); return u;
}
__device__ __forceinline__ void mma_tf32(float* c, const uint32_t* a, const uint32_t* b) {
    asm volatile(
        "mma.sync.aligned.m16n8k8.row.col.f32.tf32.tf32.f32 "
        "{%0,%1,%2,%3}, {%4,%5,%6,%7}, {%8,%9}, {%0,%1,%2,%3};"
        : "+f"(c[0]), "+f"(c[1]), "+f"(c[2]), "+f"(c[3])
        : "r"(a[0]), "r"(a[1]), "r"(a[2]), "r"(a[3]), "r"(b[0]), "r"(b[1]));
}
__device__ __forceinline__ void mma_bf16(float* c, const uint32_t* a, uint32_t b0, uint32_t b1) {
    asm volatile(
        "mma.sync.aligned.m16n8k16.row.col.f32.bf16.bf16.f32 "
        "{%0,%1,%2,%3}, {%4,%5,%6,%7}, {%8,%9}, {%0,%1,%2,%3};"
        : "+f"(c[0]), "+f"(c[1]), "+f"(c[2]), "+f"(c[3])
        : "r"(a[0]), "r"(a[1]), "r"(a[2]), "r"(a[3]), "r"(b0), "r"(b1));
}
__device__ __forceinline__ uint32_t pack_bf16(float lo, float hi) {
    __nv_bfloat162 p = __floats2bfloat162_rn(lo, hi);
    return *(uint32_t*)&p;
}

// ================= stage weights: g_wt[k][n], g_bias =================
__global__ void stage_w_kernel(const float* __restrict__ Wih_f,
                               const float* __restrict__ Wih_b,
                               const float* __restrict__ b_f,
                               const float* __restrict__ b_b) {
    int idx = blockIdx.x * blockDim.x + threadIdx.x;     // over EMBP*NTOT
    if (idx < EMBP * NTOT) {
        int k = idx / NTOT, n = idx % NTOT;
        float v = 0.0f;
        if (k < EMB) v = (n < G4) ? Wih_f[n * EMB + k] : Wih_b[(n - G4) * EMB + k];
        g_wt[idx] = v;
        if (k == 0) g_bias[n] = (n < G4) ? b_f[n] : b_b[n - G4];
    }
}

// ================= gather embeddings (padded) =================
__global__ void gather_kernel(const int* __restrict__ x,
                              const float* __restrict__ embed) {
    int m = blockIdx.x;                 // 0..MTOT-1
    int xi = x[m];
    const float* src = embed + (size_t)xi * EMB;
    float* dst = g_emb + (size_t)m * EMBP;
    for (int k = threadIdx.x; k < EMBP; k += blockDim.x)
        dst[k] = (k < EMB) ? src[k] : 0.0f;
}

// ================= input-projection GEMM (TF32 tensor cores, bf16 output) =====
#define AS_STRIDE 20
#define BS_STRIDE 136
__global__ __launch_bounds__(256) void gemm_kernel() {
    __shared__ __align__(16) uint32_t As[128 * AS_STRIDE];
    __shared__ __align__(16) uint32_t Bs[16 * BS_STRIDE];

    const int tid = threadIdx.x;
    const int m0 = blockIdx.y * 128, n0 = blockIdx.x * 128;

    const int warp = tid >> 5, lane = tid & 31;
    const int wm = (warp >> 2) * 64, wn = (warp & 3) * 32;
    const int r = lane >> 2, c = lane & 3;

    const int am = tid >> 1, akc = (tid & 1) * 8;
    const int bk = tid >> 5, bnc = (tid & 31) * 4;

    const float* Ap = g_emb + (size_t)(m0 + am) * EMBP + akc;
    const float* Bp = g_wt + (size_t)bk * NTOT + n0 + bnc;

    float acc[4][4][4];
#pragma unroll
    for (int i = 0; i < 4; ++i)
#pragma unroll
        for (int j = 0; j < 4; ++j)
#pragma unroll
            for (int q = 0; q < 4; ++q) acc[i][j][q] = 0.0f;

    float4 av0 = *(const float4*)(Ap);
    float4 av1 = *(const float4*)(Ap + 4);
    float4 bv0 = *(const float4*)(Bp);
    float4 bv1 = *(const float4*)(Bp + (size_t)8 * NTOT);

    for (int k0 = 0; k0 < EMBP; k0 += 16) {
        {
            uint4 ua0 = make_uint4(f2tf(av0.x), f2tf(av0.y), f2tf(av0.z), f2tf(av0.w));
            uint4 ua1 = make_uint4(f2tf(av1.x), f2tf(av1.y), f2tf(av1.z), f2tf(av1.w));
            *(uint4*)&As[am * AS_STRIDE + akc]     = ua0;
            *(uint4*)&As[am * AS_STRIDE + akc + 4] = ua1;
            uint4 ub0 = make_uint4(f2tf(bv0.x), f2tf(bv0.y), f2tf(bv0.z), f2tf(bv0.w));
            uint4 ub1 = make_uint4(f2tf(bv1.x), f2tf(bv1.y), f2tf(bv1.z), f2tf(bv1.w));
            *(uint4*)&Bs[bk * BS_STRIDE + bnc]       = ub0;
            *(uint4*)&Bs[(bk + 8) * BS_STRIDE + bnc] = ub1;
        }
        __syncthreads();
        if (k0 + 16 < EMBP) {
            av0 = *(const float4*)(Ap + k0 + 16);
            av1 = *(const float4*)(Ap + k0 + 20);
            bv0 = *(const float4*)(Bp + (size_t)(k0 + 16) * NTOT);
            bv1 = *(const float4*)(Bp + (size_t)(k0 + 24) * NTOT);
        }
#pragma unroll
        for (int kh = 0; kh < 16; kh += 8) {
            uint32_t af[4][4], bf[4][2];
#pragma unroll
            for (int i = 0; i < 4; ++i) {
                const uint32_t* ap = &As[(wm + i * 16 + r) * AS_STRIDE + kh + c];
                af[i][0] = ap[0];
                af[i][1] = ap[8 * AS_STRIDE];
                af[i][2] = ap[4];
                af[i][3] = ap[8 * AS_STRIDE + 4];
            }
#pragma unroll
            for (int j = 0; j < 4; ++j) {
                const uint32_t* bp = &Bs[(kh + c) * BS_STRIDE + wn + j * 8 + r];
                bf[j][0] = bp[0];
                bf[j][1] = bp[4 * BS_STRIDE];
            }
#pragma unroll
            for (int i = 0; i < 4; ++i)
#pragma unroll
                for (int j = 0; j < 4; ++j)
                    mma_tf32(acc[i][j], af[i], bf[j]);
        }
        __syncthreads();
    }

    const int dir = n0 >> 9;
    __nv_bfloat16* outb = g_gx + (size_t)dir * MTOT * G4;
#pragma unroll
    for (int j = 0; j < 4; ++j) {
        const int n = n0 + wn + j * 8 + c * 2;
        const int grow = n & 511;
        const float2 bias = *(const float2*)&g_bias[n];
#pragma unroll
        for (int i = 0; i < 4; ++i) {
            const int m = m0 + wm + i * 16 + r;
            __nv_bfloat162 p0 = __floats2bfloat162_rn(acc[i][j][0] + bias.x,
                                                      acc[i][j][1] + bias.y);
            __nv_bfloat162 p1 = __floats2bfloat162_rn(acc[i][j][2] + bias.x,
                                                      acc[i][j][3] + bias.y);
            *(__nv_bfloat162*)(outb + (size_t)m * G4 + grow)       = p0;
            *(__nv_bfloat162*)(outb + (size_t)(m + 8) * G4 + grow) = p1;
        }
    }
}

// ================= persistent LSTM recurrence (bf16 MMA, single CTA) ==========
// 32 CTAs = 2 dirs x 16 batch-groups(8). 256 threads (8 warps).
// Full Whh [512x128] lives in registers as bf16 A-fragments (m16n8k16):
// warp w owns gate rows [w*64, w*64+64) -> 4 m-tiles x 8 k-tiles x 4 regs = 128.
// No cluster: gates exchanged through CTA smem with 2 bar.sync per step.
// gx staged through smem with a 2-step-ahead LDG->STS pipeline.
// NOTE (R11 fix): ex scatter uses SCALAR float stores — with EXS=9 the row
// parity makes float2 stores hit 4-mod-8 byte addresses (misaligned-address
// trap). hBs/gxs carry __align__(16) for the u32/uint4 accesses.
#define HBS 136   // hB row stride in bf16 ([batch][unit-k], conflict-free B-frags)
#define EXS 9     // ex row stride in floats
#define GXS 512   // gxs row stride in bf16
__global__ __launch_bounds__(256, 1)
void recur_kernel(const float* __restrict__ Whh_f,
                  const float* __restrict__ Whh_b) {
    __shared__ __align__(16) __nv_bfloat16 hBs[8 * HBS];    // h as bf16, [batch][unit]
    __shared__ __align__(16) float ex[512 * EXS];           // raw Whh@h gates [gate-row][batch]
    __shared__ __align__(16) __nv_bfloat16 gxs[2][8 * GXS]; // staged gx, [batch][gate-row]

    const int cta = blockIdx.x;          // 32 CTAs
    const int dir = cta >> 4;
    const int grp = cta & 15;
    const int b0  = grp * 8;

    const int tid  = threadIdx.x;
    const int warp = tid >> 5, lane = tid & 31;
    const int gid  = lane >> 2, tid2 = lane & 3;
    const int wrow = warp * 64;

    const float* Whh = dir ? Whh_b : Whh_f;
    const __nv_bfloat16* gx = g_gx + (size_t)dir * MTOT * G4;
    float* Hbuf = g_H + (size_t)dir * 513 * BATCH * HID;

    // ---- hoist full Whh into bf16 A-fragments ----
    uint32_t wfrag[4][8][4];
#pragma unroll
    for (int mt = 0; mt < 4; ++mt) {
#pragma unroll
        for (int kt = 0; kt < 8; ++kt) {
            const int r0 = wrow + mt * 16 + gid;
            const int k0 = kt * 16 + tid2 * 2;
            const float* w0 = Whh + (size_t)r0 * HID + k0;
            const float* w1 = Whh + (size_t)(r0 + 8) * HID + k0;
            wfrag[mt][kt][0] = pack_bf16(w0[0], w0[1]);
            wfrag[mt][kt][1] = pack_bf16(w1[0], w1[1]);
            wfrag[mt][kt][2] = pack_bf16(w0[8], w0[9]);
            wfrag[mt][kt][3] = pack_bf16(w1[8], w1[9]);
        }
    }

    // ---- zero h, init c ----
    for (int i = tid; i < 8 * HBS; i += 256) hBs[i] = __float2bfloat16(0.0f);
    float cst[4] = {0.0f, 0.0f, 0.0f, 0.0f};

    // gx pipeline lanes: row bb = tid>>5, cols (tid&31)*16 .. +15
    const int gxb = tid >> 5;
    const int gxc = (tid & 31) * 16;
    auto sidx = [&](int t) { return dir ? (SEQ - 1 - t) : t; };

    uint4 pv0, pv1;
    {   // load step 0 -> smem buf 0 ; load step 1 -> regs
        const __nv_bfloat16* p = gx + ((size_t)(b0 + gxb) * SEQ + sidx(0)) * G4 + gxc;
        pv0 = *(const uint4*)p; pv1 = *(const uint4*)(p + 8);
        __nv_bfloat16* q = gxs[0] + gxb * GXS + gxc;
        *(uint4*)q = pv0; *(uint4*)(q + 8) = pv1;
        const __nv_bfloat16* p1 = gx + ((size_t)(b0 + gxb) * SEQ + sidx(1)) * G4 + gxc;
        pv0 = *(const uint4*)p1; pv1 = *(const uint4*)(p1 + 8);
    }
    __syncthreads();

    for (int t = 0; t < SEQ; ++t) {
        const int s = sidx(t);
        const int wslot = dir ? s : (s + 1);
        const int buf = t & 1;

        // ---- stage A: G = Whh @ h^T (bf16 MMA) ----
        float acc[4][4];
#pragma unroll
        for (int mt = 0; mt < 4; ++mt)
#pragma unroll
            for (int q = 0; q < 4; ++q) acc[mt][q] = 0.0f;

#pragma unroll
        for (int kt = 0; kt < 8; ++kt) {
            const __nv_bfloat16* hb = &hBs[gid * HBS + kt * 16 + tid2 * 2];
            uint32_t br0 = *(const uint32_t*)hb;
            uint32_t br1 = *(const uint32_t*)(hb + 8);
#pragma unroll
            for (int mt = 0; mt < 4; ++mt)
                mma_bf16(acc[mt], wfrag[mt][kt], br0, br1);
        }

        // scatter raw gates to ex[gate-row][batch] — scalar stores (alignment)
#pragma unroll
        for (int mt = 0; mt < 4; ++mt) {
            const int r0 = wrow + mt * 16 + gid;
            ex[r0 * EXS + tid2 * 2]           = acc[mt][0];
            ex[r0 * EXS + tid2 * 2 + 1]       = acc[mt][1];
            ex[(r0 + 8) * EXS + tid2 * 2]     = acc[mt][2];
            ex[(r0 + 8) * EXS + tid2 * 2 + 1] = acc[mt][3];
        }

        // gx pipeline: store regs (step t+1), then load step t+2
        if (t + 1 < SEQ) {
            __nv_bfloat16* q = gxs[buf ^ 1] + gxb * GXS + gxc;
            *(uint4*)q = pv0; *(uint4*)(q + 8) = pv1;
        }
        if (t + 2 < SEQ) {
            const __nv_bfloat16* p = gx + ((size_t)(b0 + gxb) * SEQ + sidx(t + 2)) * G4 + gxc;
            pv0 = *(const uint4*)p; pv1 = *(const uint4*)(p + 8);
        }
        __syncthreads();

        // ---- stage B: nonlinearity + h/c update (4 (u,b) tuples per thread) ----
        float* Hw = Hbuf + (size_t)wslot * BATCH * HID + (size_t)b0 * HID;
        const __nv_bfloat16* gxr = gxs[buf];
#pragma unroll
        for (int j = 0; j < 4; ++j) {
            const int e = tid + 256 * j;
            const int u = e >> 3, b = e & 7;
            const __nv_bfloat16* gb = gxr + b * GXS + u;
            float iv = ex[u * EXS + b]         + __bfloat162float(gb[0]);
            float fv = ex[(128 + u) * EXS + b] + __bfloat162float(gb[128]);
            float gv = ex[(256 + u) * EXS + b] + __bfloat162float(gb[256]);
            float ov = ex[(384 + u) * EXS + b] + __bfloat162float(gb[384]);
            cst[j] = sig_ap(fv) * cst[j] + sig_ap(iv) * tanh_ap(gv);
            float h = sig_ap(ov) * tanh_ap(cst[j]);
            Hw[b * HID + u] = h;
            hBs[b * HBS + u] = __float2bfloat16(h);
        }
        __syncthreads();
    }
}

// ================= output linear: y = [hf,hb] @ Wout^T + bout =================
__global__ __launch_bounds__(64) void outlin_kernel(const float* __restrict__ Wout,
                                                    const float* __restrict__ bout) {
    __shared__ float Ws[NTAG * 256];
    __shared__ float bs[NTAG];
    for (int i = threadIdx.x; i < NTAG * 256; i += 64) Ws[i] = Wout[i];
    if (threadIdx.x < NTAG) bs[threadIdx.x] = bout[threadIdx.x];
    __syncthreads();

    int m = blockIdx.x * 64 + threadIdx.x;    // 0..MTOT-1
    int b = m >> 9, s = m & 511;
    const float* hf = g_H + (size_t)(s + 1) * BATCH * HID + (size_t)b * HID;
    const float* hb = g_H + (size_t)513 * BATCH * HID + (size_t)s * BATCH * HID + (size_t)b * HID;

    float acc[NTAG];
#pragma unroll
    for (int tg = 0; tg < NTAG; ++tg) acc[tg] = bs[tg];

#pragma unroll 4
    for (int j = 0; j < 128; j += 4) {
        float4 hv = *(const float4*)(hf + j);
#pragma unroll
        for (int tg = 0; tg < NTAG; ++tg) {
            const float* wr = &Ws[tg * 256 + j];
            acc[tg] += hv.x * wr[0] + hv.y * wr[1] + hv.z * wr[2] + hv.w * wr[3];
        }
    }
#pragma unroll 4
    for (int j = 0; j < 128; j += 4) {
        float4 hv = *(const float4*)(hb + j);
#pragma unroll
        for (int tg = 0; tg < NTAG; ++tg) {
            const float* wr = &Ws[tg * 256 + 128 + j];
            acc[tg] += hv.x * wr[0] + hv.y * wr[1] + hv.z * wr[2] + hv.w * wr[3];
        }
    }
    float* yo = g_y + (size_t)m * NTAG;
#pragma unroll
    for (int tg = 0; tg < NTAG; ++tg) yo[tg] = acc[tg];
}

// ================= CRF: forward partition + gold score =================
__global__ void crf_kernel(const float* __restrict__ trans,
                           const int* __restrict__ y0,
                           float* __restrict__ out) {
    const int b = blockIdx.x;
    const int lane = threadIdx.x;     // 32 threads

    float tr[NTAG];
#pragma unroll
    for (int j = 0; j < NTAG; ++j)
        tr[j] = (lane < NTAG) ? trans[lane * NTAG + j] : NEGV;

    float sc[NTAG];
#pragma unroll
    for (int j = 0; j < NTAG; ++j) sc[j] = (j == SOS_T) ? 0.0f : NEGV;

    const float* ye = g_y + (size_t)b * SEQ * NTAG;

    for (int t = 0; t < SEQ; ++t) {
        float e = (lane < NTAG) ? ye[t * NTAG + lane] : 0.0f;
        float m = -1e30f;
        float v[NTAG];
#pragma unroll
        for (int j = 0; j < NTAG; ++j) { v[j] = sc[j] + tr[j]; m = fmaxf(m, v[j]); }
        float ssum = 0.0f;
#pragma unroll
        for (int j = 0; j < NTAG; ++j) ssum += __expf(v[j] - m);
        float nw = m + logf(ssum) + e;
#pragma unroll
        for (int j = 0; j < NTAG; ++j) sc[j] = __shfl_sync(0xFFFFFFFFu, nw, j);
    }

    float zv = (lane < NTAG) ? sc[lane] + trans[EOS_T * NTAG + lane] : -1e30f;
    float zm = zv;
#pragma unroll
    for (int o = 16; o > 0; o >>= 1) zm = fmaxf(zm, __shfl_xor_sync(0xFFFFFFFFu, zm, o));
    float ze = (lane < NTAG) ? __expf(zv - zm) : 0.0f;
#pragma unroll
    for (int o = 16; o > 0; o >>= 1) ze += __shfl_xor_sync(0xFFFFFFFFu, ze, o);
    float Z = zm + logf(ze);

    const int* yb = y0 + (size_t)b * SEQ;
    float g = 0.0f;
    for (int s = lane; s < SEQ; s += 32) {
        int yt = yb[s];
        int yp = (s == 0) ? SOS_T : yb[s - 1];
        g += ye[s * NTAG + yt] + trans[yt * NTAG + yp];
    }
#pragma unroll
    for (int o = 16; o > 0; o >>= 1) g += __shfl_xor_sync(0xFFFFFFFFu, g, o);

    if (lane == 0) {
        g += trans[EOS_T * NTAG + yb[SEQ - 1]];
        out[b] = Z - g;
    }
}

// ================= launch =================
extern "C" void kernel_launch(void* const* d_in, const int* in_sizes, int n_in,
                              void* d_out, int out_size) {
    const int*   x     = (const int*)d_in[0];
    const int*   y0    = (const int*)d_in[1];
    const float* embed = (const float*)d_in[2];
    const float* Wih_f = (const float*)d_in[3];
    const float* Whh_f = (const float*)d_in[4];
    const float* b_f   = (const float*)d_in[5];
    const float* Wih_b = (const float*)d_in[6];
    const float* Whh_b = (const float*)d_in[7];
    const float* b_b   = (const float*)d_in[8];
    const float* Wout  = (const float*)d_in[9];
    const float* bout  = (const float*)d_in[10];
    const float* trans = (const float*)d_in[11];
    float* out = (float*)d_out;

    stage_w_kernel<<<(EMBP * NTOT + 255) / 256, 256>>>(Wih_f, Wih_b, b_f, b_b);
    gather_kernel<<<MTOT, 128>>>(x, embed);
    gemm_kernel<<<dim3(8, 512), 256>>>();
    recur_kernel<<<32, 256>>>(Whh_f, Whh_b);
    outlin_kernel<<<MTOT / 64, 64>>>(Wout, bout);
    crf_kernel<<<BATCH, 32>>>(trans, y0, out);
}